// round 6
// baseline (speedup 1.0000x reference)
#include <cuda_runtime.h>
#include <math.h>

#define BATCH 2
#define SEQ   2048
#define HEADS 16
#define HD    64
#define DM    1024
#define BH    (BATCH*HEADS)

// Scratch for Q,K,V in [b,h,n,d] layout (device BSS — no allocation)
__device__ float g_q[BH * SEQ * HD];
__device__ float g_k[BH * SEQ * HD];
__device__ float g_v[BH * SEQ * HD];

// ---------------------------------------------------------------------------
// Kernel 1: QKV projection. C[4096,3072] = A[4096,1024] @ W[1024,3072] + bias
// Tile: BM=128, BN=128, BK=16. 256 threads, 8x8 microtile.
// Scatters into g_q/g_k/g_v with [b,h,n,d] layout; folds 1/sqrt(64) into Q.
// ---------------------------------------------------------------------------
#define BM 128
#define BN 128
#define BK 16

__global__ __launch_bounds__(256) void qkv_gemm(const float* __restrict__ A,
                                                const float* __restrict__ W,
                                                const float* __restrict__ bias) {
    __shared__ __align__(16) float Ast[BK][BM + 4]; // transposed A, stride 132
    __shared__ __align__(16) float Bs[BK][BN + 4];

    const int tid = threadIdx.x;
    const int tx = tid & 15;        // N dim: 16 x 8 = 128
    const int ty = tid >> 4;        // M dim: 16 x 8 = 128
    const int bm = blockIdx.y * BM;
    const int bn = blockIdx.x * BN;

    float acc[8][8] = {};

    for (int k0 = 0; k0 < DM; k0 += BK) {
        // A tile: 128x16 = 2048 elems, transposed into Ast[c][r]
        #pragma unroll
        for (int i = 0; i < 8; i++) {
            int idx = tid + i * 256;
            int r = idx >> 4, c = idx & 15;
            Ast[c][r] = A[(bm + r) * DM + k0 + c];
        }
        // B tile: 16x128 = 2048 elems
        #pragma unroll
        for (int i = 0; i < 8; i++) {
            int idx = tid + i * 256;
            int r = idx >> 7, c = idx & 127;
            Bs[r][c] = W[(k0 + r) * 3072 + bn + c];
        }
        __syncthreads();

        #pragma unroll
        for (int kk = 0; kk < BK; kk++) {
            float4 a0 = *reinterpret_cast<const float4*>(&Ast[kk][ty * 8]);
            float4 a1 = *reinterpret_cast<const float4*>(&Ast[kk][ty * 8 + 4]);
            float4 b0 = *reinterpret_cast<const float4*>(&Bs[kk][tx * 8]);
            float4 b1 = *reinterpret_cast<const float4*>(&Bs[kk][tx * 8 + 4]);
            float av[8] = {a0.x, a0.y, a0.z, a0.w, a1.x, a1.y, a1.z, a1.w};
            float bv[8] = {b0.x, b0.y, b0.z, b0.w, b1.x, b1.y, b1.z, b1.w};
            #pragma unroll
            for (int i = 0; i < 8; i++)
                #pragma unroll
                for (int j = 0; j < 8; j++)
                    acc[i][j] += av[i] * bv[j];
        }
        __syncthreads();
    }

    // Epilogue: bias add + scatter to Q/K/V buffers
    #pragma unroll
    for (int i = 0; i < 8; i++) {
        int row = bm + ty * 8 + i;
        int bt  = row >> 11;
        int tok = row & 2047;
        #pragma unroll
        for (int j = 0; j < 8; j++) {
            int col = bn + tx * 8 + j;
            float val = acc[i][j] + bias[col];
            int sec = col >> 10;            // 0=Q, 1=K, 2=V
            int rem = col & 1023;
            int h = rem >> 6;
            int ch = rem & 63;
            long dst = (((long)(bt * HEADS + h)) * SEQ + tok) * HD + ch;
            if (sec == 0)      g_q[dst] = val * 0.125f;   // fold 1/sqrt(64)
            else if (sec == 1) g_k[dst] = val;
            else               g_v[dst] = val;
        }
    }
}

// ---------------------------------------------------------------------------
// Kernel 2: flash attention. One CTA per (bh, 64-query tile).
// 256 threads; 4x4 microtile. K-tiles of 64.
// O-GEMM loads P vectorized along k (chunks of 4) — no scalar LDS.
// ---------------------------------------------------------------------------
#define SM_STRIDE 68

__global__ __launch_bounds__(256) void attn_kernel(float* __restrict__ out) {
    extern __shared__ __align__(16) float smem[];
    float* Qt = smem;                      // [ch][q]   64 x 68
    float* Kt = smem + 64 * SM_STRIDE;     // [ch][k]   64 x 68 (reused as P[q][k])
    float* Vs = smem + 2 * 64 * SM_STRIDE; // [k][d]    64 x 68

    const int tid = threadIdx.x;
    const int tx = tid & 15;
    const int ty = tid >> 4;
    const int bh = blockIdx.y;
    const int q0 = blockIdx.x * 64;

    const float* Qp = g_q + (long)bh * SEQ * HD;
    const float* Kp = g_k + (long)bh * SEQ * HD;
    const float* Vp = g_v + (long)bh * SEQ * HD;

    // Load Q tile transposed: Qt[ch][q]
    #pragma unroll
    for (int i = 0; i < 16; i++) {
        int idx = tid + i * 256;
        int r = idx >> 6, c = idx & 63;
        Qt[c * SM_STRIDE + r] = Qp[(q0 + r) * HD + c];
    }

    float o[4][4] = {};
    float m[4], l[4];
    #pragma unroll
    for (int i = 0; i < 4; i++) { m[i] = -1e30f; l[i] = 0.0f; }
    __syncthreads();

    for (int kt = 0; kt < SEQ; kt += 64) {
        // Load K (transposed) and V tiles
        #pragma unroll
        for (int i = 0; i < 16; i++) {
            int idx = tid + i * 256;
            int r = idx >> 6, c = idx & 63;
            Kt[c * SM_STRIDE + r] = Kp[(kt + r) * HD + c];
            Vs[r * SM_STRIDE + c] = Vp[(kt + r) * HD + c];
        }
        __syncthreads();

        // S = Q K^T  (scale folded into Q)
        float s[4][4] = {};
        #pragma unroll
        for (int kk = 0; kk < HD; kk++) {
            float4 qa = *reinterpret_cast<const float4*>(&Qt[kk * SM_STRIDE + ty * 4]);
            float4 kb = *reinterpret_cast<const float4*>(&Kt[kk * SM_STRIDE + tx * 4]);
            float qv[4] = {qa.x, qa.y, qa.z, qa.w};
            float kv[4] = {kb.x, kb.y, kb.z, kb.w};
            #pragma unroll
            for (int i = 0; i < 4; i++)
                #pragma unroll
                for (int j = 0; j < 4; j++)
                    s[i][j] += qv[i] * kv[j];
        }
        __syncthreads();  // all Kt reads done before P overwrites it

        // Online softmax + write P (row-major) into Kt's buffer
        #pragma unroll
        for (int i = 0; i < 4; i++) {
            float tm = s[i][0];
            #pragma unroll
            for (int j = 1; j < 4; j++) tm = fmaxf(tm, s[i][j]);
            #pragma unroll
            for (int off = 8; off > 0; off >>= 1)
                tm = fmaxf(tm, __shfl_xor_sync(0xffffffffu, tm, off, 32));

            float mnew = fmaxf(m[i], tm);
            float alpha = __expf(m[i] - mnew);
            m[i] = mnew;

            float rs = 0.0f;
            #pragma unroll
            for (int j = 0; j < 4; j++) {
                s[i][j] = __expf(s[i][j] - mnew);
                rs += s[i][j];
            }
            #pragma unroll
            for (int off = 8; off > 0; off >>= 1)
                rs += __shfl_xor_sync(0xffffffffu, rs, off, 32);
            l[i] = l[i] * alpha + rs;

            #pragma unroll
            for (int j = 0; j < 4; j++) o[i][j] *= alpha;

            *reinterpret_cast<float4*>(&Kt[(ty * 4 + i) * SM_STRIDE + tx * 4]) =
                make_float4(s[i][0], s[i][1], s[i][2], s[i][3]);
        }
        __syncthreads();

        // O += P @ V  — P loaded as float4 along k (chunks of 4)
        #pragma unroll
        for (int k4 = 0; k4 < 64; k4 += 4) {
            float4 v0 = *reinterpret_cast<const float4*>(&Vs[(k4+0) * SM_STRIDE + tx * 4]);
            float4 v1 = *reinterpret_cast<const float4*>(&Vs[(k4+1) * SM_STRIDE + tx * 4]);
            float4 v2 = *reinterpret_cast<const float4*>(&Vs[(k4+2) * SM_STRIDE + tx * 4]);
            float4 v3 = *reinterpret_cast<const float4*>(&Vs[(k4+3) * SM_STRIDE + tx * 4]);
            #pragma unroll
            for (int i = 0; i < 4; i++) {
                float4 p4 = *reinterpret_cast<const float4*>(&Kt[(ty * 4 + i) * SM_STRIDE + k4]);
                o[i][0] += p4.x * v0.x + p4.y * v1.x + p4.z * v2.x + p4.w * v3.x;
                o[i][1] += p4.x * v0.y + p4.y * v1.y + p4.z * v2.y + p4.w * v3.y;
                o[i][2] += p4.x * v0.z + p4.y * v1.z + p4.z * v2.z + p4.w * v3.z;
                o[i][3] += p4.x * v0.w + p4.y * v1.w + p4.z * v2.w + p4.w * v3.w;
            }
        }
        __syncthreads();
    }

    // Epilogue: normalize and write [b, n, h*64 + d]
    const int b = bh >> 4;
    const int h = bh & 15;
    #pragma unroll
    for (int i = 0; i < 4; i++) {
        float inv = 1.0f / l[i];
        int tok = q0 + ty * 4 + i;
        long base = ((long)(b * SEQ + tok)) * DM + h * HD + tx * 4;
        *reinterpret_cast<float4*>(&out[base]) =
            make_float4(o[i][0] * inv, o[i][1] * inv, o[i][2] * inv, o[i][3] * inv);
    }
}

// ---------------------------------------------------------------------------
extern "C" void kernel_launch(void* const* d_in, const int* in_sizes, int n_in,
                              void* d_out, int out_size) {
    const float* tokens = (const float*)d_in[0];   // [2,2048,1024]
    const float* w_qkv  = (const float*)d_in[1];   // [1024,3072]
    const float* b_qkv  = (const float*)d_in[2];   // [3072]
    float* out = (float*)d_out;                    // [2,2048,1024]

    const int attn_smem = 3 * 64 * SM_STRIDE * (int)sizeof(float); // 52224 B
    cudaFuncSetAttribute(attn_kernel,
                         cudaFuncAttributeMaxDynamicSharedMemorySize, attn_smem);

    dim3 g1(3072 / BN, 4096 / BM);   // (24, 32)
    qkv_gemm<<<g1, 256>>>(tokens, w_qkv, b_qkv);

    dim3 g2(SEQ / 64, BH);           // (32, 32)
    attn_kernel<<<g2, 256, attn_smem>>>(out);
}

// round 10
// speedup vs baseline: 1.3855x; 1.3855x over previous
#include <cuda_runtime.h>
#include <cuda_bf16.h>
#include <cstdint>
#include <math.h>

#define BATCH 2
#define SEQ   2048
#define HEADS 16
#define HD    64
#define DM    1024
#define BH    (BATCH*HEADS)

// ---------------------------------------------------------------------------
// Device scratch (BSS — no allocation)
// ---------------------------------------------------------------------------
__device__ float g_q[BH * SEQ * HD];
__device__ float g_k[BH * SEQ * HD];
__device__ float g_v[BH * SEQ * HD];
// bf16 hi/lo split operands. A: [4096,1024] row-major; W: transposed to [3072,1024]
__device__ __align__(16) __nv_bfloat16 g_ahi[4096 * 1024];
__device__ __align__(16) __nv_bfloat16 g_alo[4096 * 1024];
__device__ __align__(16) __nv_bfloat16 g_whi[3072 * 1024];
__device__ __align__(16) __nv_bfloat16 g_wlo[3072 * 1024];

// ---------------------------------------------------------------------------
// Split kernels: fp32 -> bf16 hi + bf16 lo
// ---------------------------------------------------------------------------
__global__ __launch_bounds__(256) void split_a(const float* __restrict__ A) {
    int i = blockIdx.x * 256 + threadIdx.x;        // 1,048,576 float4s
    float4 v = reinterpret_cast<const float4*>(A)[i];
    __nv_bfloat16 h0 = __float2bfloat16(v.x), h1 = __float2bfloat16(v.y);
    __nv_bfloat16 h2 = __float2bfloat16(v.z), h3 = __float2bfloat16(v.w);
    __nv_bfloat16 l0 = __float2bfloat16(v.x - __bfloat162float(h0));
    __nv_bfloat16 l1 = __float2bfloat16(v.y - __bfloat162float(h1));
    __nv_bfloat16 l2 = __float2bfloat16(v.z - __bfloat162float(h2));
    __nv_bfloat16 l3 = __float2bfloat16(v.w - __bfloat162float(h3));
    __nv_bfloat162* ph = reinterpret_cast<__nv_bfloat162*>(g_ahi);
    __nv_bfloat162* pl = reinterpret_cast<__nv_bfloat162*>(g_alo);
    ph[2 * i]     = __nv_bfloat162(h0, h1);
    ph[2 * i + 1] = __nv_bfloat162(h2, h3);
    pl[2 * i]     = __nv_bfloat162(l0, l1);
    pl[2 * i + 1] = __nv_bfloat162(l2, l3);
}

// W [1024,3072] row-major -> Whi/Wlo [3072,1024] (K contiguous per output row)
__global__ __launch_bounds__(256) void split_w(const float* __restrict__ W) {
    __shared__ float t[32][33];
    const int tx = threadIdx.x & 31, ty = threadIdx.x >> 5;  // 32 x 8
    const int n0 = blockIdx.x * 32, k0 = blockIdx.y * 32;
    #pragma unroll
    for (int r = 0; r < 32; r += 8)
        t[ty + r][tx] = W[(long)(k0 + ty + r) * 3072 + n0 + tx];
    __syncthreads();
    #pragma unroll
    for (int r = 0; r < 32; r += 8) {
        int n = n0 + ty + r, k = k0 + tx;
        float x = t[tx][ty + r];
        __nv_bfloat16 h = __float2bfloat16(x);
        __nv_bfloat16 l = __float2bfloat16(x - __bfloat162float(h));
        g_whi[(long)n * 1024 + k] = h;
        g_wlo[(long)n * 1024 + k] = l;
    }
}

// ---------------------------------------------------------------------------
// mma.sync bf16 helper: D(16x8,f32) += A(16x16,bf16) * B(16x8,bf16)
// A row-major fragment, B col-major fragment (B stored as [n][k] row-major).
// ---------------------------------------------------------------------------
__device__ __forceinline__ void mma_bf16(float* d, const uint32_t* a, const uint32_t* b) {
    asm volatile(
        "mma.sync.aligned.m16n8k16.row.col.f32.bf16.bf16.f32 "
        "{%0,%1,%2,%3}, {%4,%5,%6,%7}, {%8,%9}, {%0,%1,%2,%3};"
        : "+f"(d[0]), "+f"(d[1]), "+f"(d[2]), "+f"(d[3])
        : "r"(a[0]), "r"(a[1]), "r"(a[2]), "r"(a[3]), "r"(b[0]), "r"(b[1]));
}

// ---------------------------------------------------------------------------
// Kernel 1: QKV GEMM via HMMA. C[4096,3072] = A @ W^T(view) + bias.
// CTA 128x128, 8 warps (4m x 2n), warp tile 32x64. K-chunks of 32.
// 3-term hi/lo split per k16: hi*hi + hi*lo + lo*hi, fp32 accum.
// ---------------------------------------------------------------------------
#define KC 32
#define ASTR 40   // smem row stride in bf16 (pad for conflict-free fragment LDS)

__global__ __launch_bounds__(256) void qkv_mma(const float* __restrict__ bias) {
    __shared__ __align__(16) __nv_bfloat16 sA[2][128 * ASTR];  // [hi/lo][row*ASTR+k]
    __shared__ __align__(16) __nv_bfloat16 sB[2][128 * ASTR];

    const int tid = threadIdx.x;
    const int wid = tid >> 5, lane = tid & 31;
    const int wm = (wid & 3) * 32;     // warp m offset in CTA tile
    const int wn = (wid >> 2) * 64;    // warp n offset in CTA tile
    const int bm = blockIdx.y * 128;
    const int bn = blockIdx.x * 128;
    const int lr = lane >> 2;          // 0..7
    const int lc = 2 * (lane & 3);     // 0,2,4,6

    float acc[2][8][4];
    #pragma unroll
    for (int mi = 0; mi < 2; mi++)
        #pragma unroll
        for (int nj = 0; nj < 8; nj++)
            #pragma unroll
            for (int q = 0; q < 4; q++) acc[mi][nj][q] = 0.0f;

    for (int ck = 0; ck < DM / KC; ck++) {
        const int k0 = ck * KC;
        // Load A/B hi+lo tiles: 128 rows x 32 bf16 each = 512 uint4 per matrix
        #pragma unroll
        for (int i = 0; i < 2; i++) {
            int idx = tid + i * 256;          // 0..511
            int r = idx >> 2, c = (idx & 3) * 8;
            long srcA = (long)(bm + r) * DM + k0 + c;
            long srcB = (long)(bn + r) * DM + k0 + c;
            *reinterpret_cast<uint4*>(&sA[0][r * ASTR + c]) =
                *reinterpret_cast<const uint4*>(g_ahi + srcA);
            *reinterpret_cast<uint4*>(&sA[1][r * ASTR + c]) =
                *reinterpret_cast<const uint4*>(g_alo + srcA);
            *reinterpret_cast<uint4*>(&sB[0][r * ASTR + c]) =
                *reinterpret_cast<const uint4*>(g_whi + srcB);
            *reinterpret_cast<uint4*>(&sB[1][r * ASTR + c]) =
                *reinterpret_cast<const uint4*>(g_wlo + srcB);
        }
        __syncthreads();

        #pragma unroll
        for (int ks = 0; ks < 2; ks++) {
            const int kk = ks * 16 + lc;
            // A fragments for both m-tiles, hi and lo
            uint32_t ah[2][4], al[2][4];
            #pragma unroll
            for (int mi = 0; mi < 2; mi++) {
                int r = wm + mi * 16 + lr;
                ah[mi][0] = *reinterpret_cast<uint32_t*>(&sA[0][r * ASTR + kk]);
                ah[mi][1] = *reinterpret_cast<uint32_t*>(&sA[0][(r + 8) * ASTR + kk]);
                ah[mi][2] = *reinterpret_cast<uint32_t*>(&sA[0][r * ASTR + kk + 8]);
                ah[mi][3] = *reinterpret_cast<uint32_t*>(&sA[0][(r + 8) * ASTR + kk + 8]);
                al[mi][0] = *reinterpret_cast<uint32_t*>(&sA[1][r * ASTR + kk]);
                al[mi][1] = *reinterpret_cast<uint32_t*>(&sA[1][(r + 8) * ASTR + kk]);
                al[mi][2] = *reinterpret_cast<uint32_t*>(&sA[1][r * ASTR + kk + 8]);
                al[mi][3] = *reinterpret_cast<uint32_t*>(&sA[1][(r + 8) * ASTR + kk + 8]);
            }
            #pragma unroll
            for (int nj = 0; nj < 8; nj++) {
                int n = wn + nj * 8 + lr;
                uint32_t bh[2], bl[2];
                bh[0] = *reinterpret_cast<uint32_t*>(&sB[0][n * ASTR + kk]);
                bh[1] = *reinterpret_cast<uint32_t*>(&sB[0][n * ASTR + kk + 8]);
                bl[0] = *reinterpret_cast<uint32_t*>(&sB[1][n * ASTR + kk]);
                bl[1] = *reinterpret_cast<uint32_t*>(&sB[1][n * ASTR + kk + 8]);
                #pragma unroll
                for (int mi = 0; mi < 2; mi++) {
                    mma_bf16(acc[mi][nj], ah[mi], bh);
                    mma_bf16(acc[mi][nj], ah[mi], bl);
                    mma_bf16(acc[mi][nj], al[mi], bh);
                }
            }
        }
        __syncthreads();
    }

    // Epilogue: bias + scatter. Whole CTA tile lies in one of Q/K/V (bn % 1024 block).
    const int sec = bn >> 10;                    // 0=Q, 1=K, 2=V
    const float scale = (sec == 0) ? 0.125f : 1.0f;
    float* dstb = (sec == 0) ? g_q : ((sec == 1) ? g_k : g_v);
    #pragma unroll
    for (int nj = 0; nj < 8; nj++) {
        int col = bn + wn + nj * 8 + lc;         // even column
        int rem = col & 1023;
        int h = rem >> 6, ch = rem & 63;
        float bv0 = bias[col], bv1 = bias[col + 1];
        #pragma unroll
        for (int mi = 0; mi < 2; mi++) {
            #pragma unroll
            for (int half = 0; half < 2; half++) {
                int row = bm + wm + mi * 16 + lr + half * 8;
                int bt = row >> 11, tok = row & 2047;
                long base = (((long)(bt * HEADS + h)) * SEQ + tok) * HD + ch;
                float2 v;
                v.x = (acc[mi][nj][half * 2 + 0] + bv0) * scale;
                v.y = (acc[mi][nj][half * 2 + 1] + bv1) * scale;
                *reinterpret_cast<float2*>(dstb + base) = v;
            }
        }
    }
}

// ---------------------------------------------------------------------------
// Kernel 2: flash attention — R2 version verbatim (measured 963us).
// ---------------------------------------------------------------------------
#define SM_STRIDE 68

__global__ __launch_bounds__(256) void attn_kernel(float* __restrict__ out) {
    extern __shared__ __align__(16) float smem[];
    float* Qt = smem;                      // [ch][q]   64 x 68
    float* Kt = smem + 64 * SM_STRIDE;     // [ch][k]   64 x 68  (reused as P[q][k])
    float* Vs = smem + 2 * 64 * SM_STRIDE; // [k][d]    64 x 68

    const int tid = threadIdx.x;
    const int tx = tid & 15;
    const int ty = tid >> 4;
    const int bh = blockIdx.y;
    const int q0 = blockIdx.x * 64;

    const float* Qp = g_q + (long)bh * SEQ * HD;
    const float* Kp = g_k + (long)bh * SEQ * HD;
    const float* Vp = g_v + (long)bh * SEQ * HD;

    #pragma unroll
    for (int i = 0; i < 16; i++) {
        int idx = tid + i * 256;
        int r = idx >> 6, c = idx & 63;
        Qt[c * SM_STRIDE + r] = Qp[(q0 + r) * HD + c];
    }

    float o[4][4] = {};
    float m[4], l[4];
    #pragma unroll
    for (int i = 0; i < 4; i++) { m[i] = -1e30f; l[i] = 0.0f; }
    __syncthreads();

    for (int kt = 0; kt < SEQ; kt += 64) {
        #pragma unroll
        for (int i = 0; i < 16; i++) {
            int idx = tid + i * 256;
            int r = idx >> 6, c = idx & 63;
            Kt[c * SM_STRIDE + r] = Kp[(kt + r) * HD + c];
            Vs[r * SM_STRIDE + c] = Vp[(kt + r) * HD + c];
        }
        __syncthreads();

        float s[4][4] = {};
        #pragma unroll
        for (int kk = 0; kk < HD; kk++) {
            float4 qa = *reinterpret_cast<const float4*>(&Qt[kk * SM_STRIDE + ty * 4]);
            float4 kb = *reinterpret_cast<const float4*>(&Kt[kk * SM_STRIDE + tx * 4]);
            float qv[4] = {qa.x, qa.y, qa.z, qa.w};
            float kv[4] = {kb.x, kb.y, kb.z, kb.w};
            #pragma unroll
            for (int i = 0; i < 4; i++)
                #pragma unroll
                for (int j = 0; j < 4; j++)
                    s[i][j] += qv[i] * kv[j];
        }
        __syncthreads();

        #pragma unroll
        for (int i = 0; i < 4; i++) {
            float tm = s[i][0];
            #pragma unroll
            for (int j = 1; j < 4; j++) tm = fmaxf(tm, s[i][j]);
            #pragma unroll
            for (int off = 8; off > 0; off >>= 1)
                tm = fmaxf(tm, __shfl_xor_sync(0xffffffffu, tm, off, 32));

            float mnew = fmaxf(m[i], tm);
            float alpha = __expf(m[i] - mnew);
            m[i] = mnew;

            float rs = 0.0f;
            #pragma unroll
            for (int j = 0; j < 4; j++) {
                s[i][j] = __expf(s[i][j] - mnew);
                rs += s[i][j];
            }
            #pragma unroll
            for (int off = 8; off > 0; off >>= 1)
                rs += __shfl_xor_sync(0xffffffffu, rs, off, 32);
            l[i] = l[i] * alpha + rs;

            #pragma unroll
            for (int j = 0; j < 4; j++) o[i][j] *= alpha;

            *reinterpret_cast<float4*>(&Kt[(ty * 4 + i) * SM_STRIDE + tx * 4]) =
                make_float4(s[i][0], s[i][1], s[i][2], s[i][3]);
        }
        __syncthreads();

        #pragma unroll
        for (int kk = 0; kk < 64; kk++) {
            float pa[4];
            #pragma unroll
            for (int i = 0; i < 4; i++) pa[i] = Kt[(ty * 4 + i) * SM_STRIDE + kk];
            float4 vb4 = *reinterpret_cast<const float4*>(&Vs[kk * SM_STRIDE + tx * 4]);
            float vv[4] = {vb4.x, vb4.y, vb4.z, vb4.w};
            #pragma unroll
            for (int i = 0; i < 4; i++)
                #pragma unroll
                for (int j = 0; j < 4; j++)
                    o[i][j] += pa[i] * vv[j];
        }
        __syncthreads();
    }

    const int b = bh >> 4;
    const int h = bh & 15;
    #pragma unroll
    for (int i = 0; i < 4; i++) {
        float inv = 1.0f / l[i];
        int tok = q0 + ty * 4 + i;
        long base = ((long)(b * SEQ + tok)) * DM + h * HD + tx * 4;
        *reinterpret_cast<float4*>(&out[base]) =
            make_float4(o[i][0] * inv, o[i][1] * inv, o[i][2] * inv, o[i][3] * inv);
    }
}

// ---------------------------------------------------------------------------
extern "C" void kernel_launch(void* const* d_in, const int* in_sizes, int n_in,
                              void* d_out, int out_size) {
    const float* tokens = (const float*)d_in[0];   // [2,2048,1024]
    const float* w_qkv  = (const float*)d_in[1];   // [1024,3072]
    const float* b_qkv  = (const float*)d_in[2];   // [3072]
    float* out = (float*)d_out;                    // [2,2048,1024]

    const int attn_smem = 3 * 64 * SM_STRIDE * (int)sizeof(float); // 52224 B
    cudaFuncSetAttribute(attn_kernel,
                         cudaFuncAttributeMaxDynamicSharedMemorySize, attn_smem);

    split_a<<<4096, 256>>>(tokens);
    split_w<<<dim3(96, 32), 256>>>(w_qkv);

    dim3 gg(3072 / 128, 4096 / 128);   // (24, 32)
    qkv_mma<<<gg, 256>>>(b_qkv);

    dim3 g2(SEQ / 64, BH);             // (32, 32)
    attn_kernel<<<g2, 256, attn_smem>>>(out);
}

// round 12
// speedup vs baseline: 2.3246x; 1.6779x over previous
#include <cuda_runtime.h>
#include <cuda_bf16.h>
#include <cstdint>
#include <math.h>

#define BATCH 2
#define SEQ   2048
#define HEADS 16
#define HD    64
#define DM    1024
#define BH    (BATCH*HEADS)

// ---------------------------------------------------------------------------
// Device scratch (BSS — no allocation)
// ---------------------------------------------------------------------------
__device__ __align__(16) __nv_bfloat16 g_ahi[4096 * 1024];
__device__ __align__(16) __nv_bfloat16 g_alo[4096 * 1024];
__device__ __align__(16) __nv_bfloat16 g_whi[3072 * 1024];
__device__ __align__(16) __nv_bfloat16 g_wlo[3072 * 1024];
// Q/K/V in [bh][seq][d], bf16 hi/lo pairs (written by qkv_mma epilogue)
__device__ __align__(16) __nv_bfloat16 g_qhi[BH * SEQ * HD];
__device__ __align__(16) __nv_bfloat16 g_qlo[BH * SEQ * HD];
__device__ __align__(16) __nv_bfloat16 g_khi[BH * SEQ * HD];
__device__ __align__(16) __nv_bfloat16 g_klo[BH * SEQ * HD];
__device__ __align__(16) __nv_bfloat16 g_vhi[BH * SEQ * HD];
__device__ __align__(16) __nv_bfloat16 g_vlo[BH * SEQ * HD];

// ---------------------------------------------------------------------------
// Split kernels: fp32 -> bf16 hi + bf16 lo
// ---------------------------------------------------------------------------
__global__ __launch_bounds__(256) void split_a(const float* __restrict__ A) {
    int i = blockIdx.x * 256 + threadIdx.x;        // 1,048,576 float4s
    float4 v = reinterpret_cast<const float4*>(A)[i];
    __nv_bfloat16 h0 = __float2bfloat16(v.x), h1 = __float2bfloat16(v.y);
    __nv_bfloat16 h2 = __float2bfloat16(v.z), h3 = __float2bfloat16(v.w);
    __nv_bfloat16 l0 = __float2bfloat16(v.x - __bfloat162float(h0));
    __nv_bfloat16 l1 = __float2bfloat16(v.y - __bfloat162float(h1));
    __nv_bfloat16 l2 = __float2bfloat16(v.z - __bfloat162float(h2));
    __nv_bfloat16 l3 = __float2bfloat16(v.w - __bfloat162float(h3));
    __nv_bfloat162* ph = reinterpret_cast<__nv_bfloat162*>(g_ahi);
    __nv_bfloat162* pl = reinterpret_cast<__nv_bfloat162*>(g_alo);
    ph[2 * i]     = __nv_bfloat162(h0, h1);
    ph[2 * i + 1] = __nv_bfloat162(h2, h3);
    pl[2 * i]     = __nv_bfloat162(l0, l1);
    pl[2 * i + 1] = __nv_bfloat162(l2, l3);
}

// W [1024,3072] row-major -> Whi/Wlo [3072,1024] (K contiguous per output row)
__global__ __launch_bounds__(256) void split_w(const float* __restrict__ W) {
    __shared__ float t[32][33];
    const int tx = threadIdx.x & 31, ty = threadIdx.x >> 5;  // 32 x 8
    const int n0 = blockIdx.x * 32, k0 = blockIdx.y * 32;
    #pragma unroll
    for (int r = 0; r < 32; r += 8)
        t[ty + r][tx] = W[(long)(k0 + ty + r) * 3072 + n0 + tx];
    __syncthreads();
    #pragma unroll
    for (int r = 0; r < 32; r += 8) {
        int n = n0 + ty + r, k = k0 + tx;
        float x = t[tx][ty + r];
        __nv_bfloat16 h = __float2bfloat16(x);
        __nv_bfloat16 l = __float2bfloat16(x - __bfloat162float(h));
        g_whi[(long)n * 1024 + k] = h;
        g_wlo[(long)n * 1024 + k] = l;
    }
}

// ---------------------------------------------------------------------------
// mma.sync bf16: D(16x8,f32) += A(16x16,bf16,row) * B(16x8,bf16,col)
// ---------------------------------------------------------------------------
__device__ __forceinline__ void mma_bf16(float* d, const uint32_t* a, const uint32_t* b) {
    asm volatile(
        "mma.sync.aligned.m16n8k16.row.col.f32.bf16.bf16.f32 "
        "{%0,%1,%2,%3}, {%4,%5,%6,%7}, {%8,%9}, {%0,%1,%2,%3};"
        : "+f"(d[0]), "+f"(d[1]), "+f"(d[2]), "+f"(d[3])
        : "r"(a[0]), "r"(a[1]), "r"(a[2]), "r"(a[3]), "r"(b[0]), "r"(b[1]));
}

__device__ __forceinline__ uint32_t pack_bf16x2(float x0, float x1) {
    __nv_bfloat162 p(__float2bfloat16(x0), __float2bfloat16(x1));
    return *reinterpret_cast<uint32_t*>(&p);
}

// ---------------------------------------------------------------------------
// Kernel 1: QKV GEMM via HMMA (measured-good in R10); epilogue now emits
// bf16 hi/lo Q/K/V directly (scale 0.125 folded into Q before split).
// ---------------------------------------------------------------------------
#define KC 32
#define ASTR 40

__global__ __launch_bounds__(256) void qkv_mma(const float* __restrict__ bias) {
    __shared__ __align__(16) __nv_bfloat16 sA[2][128 * ASTR];
    __shared__ __align__(16) __nv_bfloat16 sB[2][128 * ASTR];

    const int tid = threadIdx.x;
    const int wid = tid >> 5, lane = tid & 31;
    const int wm = (wid & 3) * 32;
    const int wn = (wid >> 2) * 64;
    const int bm = blockIdx.y * 128;
    const int bn = blockIdx.x * 128;
    const int lr = lane >> 2;
    const int lc = 2 * (lane & 3);

    float acc[2][8][4];
    #pragma unroll
    for (int mi = 0; mi < 2; mi++)
        #pragma unroll
        for (int nj = 0; nj < 8; nj++)
            #pragma unroll
            for (int q = 0; q < 4; q++) acc[mi][nj][q] = 0.0f;

    for (int ck = 0; ck < DM / KC; ck++) {
        const int k0 = ck * KC;
        #pragma unroll
        for (int i = 0; i < 2; i++) {
            int idx = tid + i * 256;
            int r = idx >> 2, c = (idx & 3) * 8;
            long srcA = (long)(bm + r) * DM + k0 + c;
            long srcB = (long)(bn + r) * DM + k0 + c;
            *reinterpret_cast<uint4*>(&sA[0][r * ASTR + c]) =
                *reinterpret_cast<const uint4*>(g_ahi + srcA);
            *reinterpret_cast<uint4*>(&sA[1][r * ASTR + c]) =
                *reinterpret_cast<const uint4*>(g_alo + srcA);
            *reinterpret_cast<uint4*>(&sB[0][r * ASTR + c]) =
                *reinterpret_cast<const uint4*>(g_whi + srcB);
            *reinterpret_cast<uint4*>(&sB[1][r * ASTR + c]) =
                *reinterpret_cast<const uint4*>(g_wlo + srcB);
        }
        __syncthreads();

        #pragma unroll
        for (int ks = 0; ks < 2; ks++) {
            const int kk = ks * 16 + lc;
            uint32_t ah[2][4], al[2][4];
            #pragma unroll
            for (int mi = 0; mi < 2; mi++) {
                int r = wm + mi * 16 + lr;
                ah[mi][0] = *reinterpret_cast<uint32_t*>(&sA[0][r * ASTR + kk]);
                ah[mi][1] = *reinterpret_cast<uint32_t*>(&sA[0][(r + 8) * ASTR + kk]);
                ah[mi][2] = *reinterpret_cast<uint32_t*>(&sA[0][r * ASTR + kk + 8]);
                ah[mi][3] = *reinterpret_cast<uint32_t*>(&sA[0][(r + 8) * ASTR + kk + 8]);
                al[mi][0] = *reinterpret_cast<uint32_t*>(&sA[1][r * ASTR + kk]);
                al[mi][1] = *reinterpret_cast<uint32_t*>(&sA[1][(r + 8) * ASTR + kk]);
                al[mi][2] = *reinterpret_cast<uint32_t*>(&sA[1][r * ASTR + kk + 8]);
                al[mi][3] = *reinterpret_cast<uint32_t*>(&sA[1][(r + 8) * ASTR + kk + 8]);
            }
            #pragma unroll
            for (int nj = 0; nj < 8; nj++) {
                int n = wn + nj * 8 + lr;
                uint32_t bh2[2], bl2[2];
                bh2[0] = *reinterpret_cast<uint32_t*>(&sB[0][n * ASTR + kk]);
                bh2[1] = *reinterpret_cast<uint32_t*>(&sB[0][n * ASTR + kk + 8]);
                bl2[0] = *reinterpret_cast<uint32_t*>(&sB[1][n * ASTR + kk]);
                bl2[1] = *reinterpret_cast<uint32_t*>(&sB[1][n * ASTR + kk + 8]);
                #pragma unroll
                for (int mi = 0; mi < 2; mi++) {
                    mma_bf16(acc[mi][nj], ah[mi], bh2);
                    mma_bf16(acc[mi][nj], ah[mi], bl2);
                    mma_bf16(acc[mi][nj], al[mi], bh2);
                }
            }
        }
        __syncthreads();
    }

    // Epilogue: bias (+scale for Q), split to bf16 hi/lo, store pairs.
    const int sec = bn >> 10;                    // 0=Q, 1=K, 2=V
    const float scale = (sec == 0) ? 0.125f : 1.0f;
    __nv_bfloat16* dh = (sec == 0) ? g_qhi : ((sec == 1) ? g_khi : g_vhi);
    __nv_bfloat16* dl = (sec == 0) ? g_qlo : ((sec == 1) ? g_klo : g_vlo);
    #pragma unroll
    for (int nj = 0; nj < 8; nj++) {
        int col = bn + wn + nj * 8 + lc;         // even
        int rem = col & 1023;
        int h = rem >> 6, ch = rem & 63;
        float bv0 = bias[col], bv1 = bias[col + 1];
        #pragma unroll
        for (int mi = 0; mi < 2; mi++) {
            #pragma unroll
            for (int half = 0; half < 2; half++) {
                int row = bm + wm + mi * 16 + lr + half * 8;
                int bt = row >> 11, tok = row & 2047;
                long base = (((long)(bt * HEADS + h)) * SEQ + tok) * HD + ch;
                float v0 = (acc[mi][nj][half * 2 + 0] + bv0) * scale;
                float v1 = (acc[mi][nj][half * 2 + 1] + bv1) * scale;
                __nv_bfloat16 h0 = __float2bfloat16(v0);
                __nv_bfloat16 h1 = __float2bfloat16(v1);
                __nv_bfloat16 e0 = __float2bfloat16(v0 - __bfloat162float(h0));
                __nv_bfloat16 e1 = __float2bfloat16(v1 - __bfloat162float(h1));
                *reinterpret_cast<__nv_bfloat162*>(dh + base) = __nv_bfloat162(h0, h1);
                *reinterpret_cast<__nv_bfloat162*>(dl + base) = __nv_bfloat162(e0, e1);
            }
        }
    }
}

// ---------------------------------------------------------------------------
// Kernel 2: HMMA flash attention. CTA = (bh, 128-q tile), 8 warps x 16 rows.
// Key-tiles of 64. S and P@V both 3-term hi/lo bf16 MMAs, fp32 accum.
// P stays in registers (accumulator layout == A-fragment layout).
// ---------------------------------------------------------------------------
#define STR 72   // smem row stride (bf16): 8 rows x 4 banks -> conflict-free frags
// smem offsets in bf16 units
#define SQH 0
#define SQL (128 * STR)
#define SKH (2 * 128 * STR)
#define SKL (SKH + 64 * STR)
#define SVH (SKL + 64 * STR)
#define SVL (SVH + 64 * STR)
#define ATTN_SMEM_BF16 (SVL + 64 * STR)

__global__ __launch_bounds__(256, 1) void attn_mma(float* __restrict__ out) {
    extern __shared__ __align__(16) __nv_bfloat16 sm[];

    const int tid = threadIdx.x;
    const int wid = tid >> 5, lane = tid & 31;
    const int lr = lane >> 2;
    const int lc = 2 * (lane & 3);
    const int bh = blockIdx.y;
    const int q0 = blockIdx.x * 128;
    const int wr = wid * 16;

    const long qoff = (long)bh * SEQ * HD + (long)q0 * HD;
    const long kvoff = (long)bh * SEQ * HD;

    // Load Q hi/lo: 128 x 64 bf16 each = 1024 uint4 per matrix
    #pragma unroll
    for (int i = 0; i < 4; i++) {
        int idx = tid + i * 256;
        int r = idx >> 3, c = (idx & 7) * 8;
        *reinterpret_cast<uint4*>(&sm[SQH + r * STR + c]) =
            *reinterpret_cast<const uint4*>(g_qhi + qoff + r * 64 + c);
        *reinterpret_cast<uint4*>(&sm[SQL + r * STR + c]) =
            *reinterpret_cast<const uint4*>(g_qlo + qoff + r * 64 + c);
    }

    float accO[8][4];
    #pragma unroll
    for (int nj = 0; nj < 8; nj++)
        #pragma unroll
        for (int q = 0; q < 4; q++) accO[nj][q] = 0.0f;
    float m0 = -1e30f, m1 = -1e30f, l0 = 0.0f, l1 = 0.0f;

    for (int kt = 0; kt < SEQ; kt += 64) {
        // K hi/lo: 64x64 = 512 uint4 per matrix
        #pragma unroll
        for (int i = 0; i < 2; i++) {
            int idx = tid + i * 256;
            int r = idx >> 3, c = (idx & 7) * 8;
            *reinterpret_cast<uint4*>(&sm[SKH + r * STR + c]) =
                *reinterpret_cast<const uint4*>(g_khi + kvoff + (long)(kt + r) * 64 + c);
            *reinterpret_cast<uint4*>(&sm[SKL + r * STR + c]) =
                *reinterpret_cast<const uint4*>(g_klo + kvoff + (long)(kt + r) * 64 + c);
        }
        // V transposed into sVt[d][key]
        {
            int key = tid & 63, db = (tid >> 6) * 16;
            uint4 vh0 = *reinterpret_cast<const uint4*>(g_vhi + kvoff + (long)(kt + key) * 64 + db);
            uint4 vh1 = *reinterpret_cast<const uint4*>(g_vhi + kvoff + (long)(kt + key) * 64 + db + 8);
            uint4 vl0 = *reinterpret_cast<const uint4*>(g_vlo + kvoff + (long)(kt + key) * 64 + db);
            uint4 vl1 = *reinterpret_cast<const uint4*>(g_vlo + kvoff + (long)(kt + key) * 64 + db + 8);
            const __nv_bfloat16* ph0 = reinterpret_cast<const __nv_bfloat16*>(&vh0);
            const __nv_bfloat16* ph1 = reinterpret_cast<const __nv_bfloat16*>(&vh1);
            const __nv_bfloat16* pl0 = reinterpret_cast<const __nv_bfloat16*>(&vl0);
            const __nv_bfloat16* pl1 = reinterpret_cast<const __nv_bfloat16*>(&vl1);
            #pragma unroll
            for (int j = 0; j < 8; j++) {
                sm[SVH + (db + j) * STR + key] = ph0[j];
                sm[SVH + (db + 8 + j) * STR + key] = ph1[j];
                sm[SVL + (db + j) * STR + key] = pl0[j];
                sm[SVL + (db + 8 + j) * STR + key] = pl1[j];
            }
        }
        __syncthreads();

        // ---- S = Q K^T (3-term split), fp32 accum ----
        float accS[8][4];
        #pragma unroll
        for (int nj = 0; nj < 8; nj++)
            #pragma unroll
            for (int q = 0; q < 4; q++) accS[nj][q] = 0.0f;

        #pragma unroll
        for (int ks = 0; ks < 4; ks++) {
            const int kk = ks * 16 + lc;
            uint32_t ah[4], al[4];
            ah[0] = *reinterpret_cast<uint32_t*>(&sm[SQH + (wr + lr) * STR + kk]);
            ah[1] = *reinterpret_cast<uint32_t*>(&sm[SQH + (wr + lr + 8) * STR + kk]);
            ah[2] = *reinterpret_cast<uint32_t*>(&sm[SQH + (wr + lr) * STR + kk + 8]);
            ah[3] = *reinterpret_cast<uint32_t*>(&sm[SQH + (wr + lr + 8) * STR + kk + 8]);
            al[0] = *reinterpret_cast<uint32_t*>(&sm[SQL + (wr + lr) * STR + kk]);
            al[1] = *reinterpret_cast<uint32_t*>(&sm[SQL + (wr + lr + 8) * STR + kk]);
            al[2] = *reinterpret_cast<uint32_t*>(&sm[SQL + (wr + lr) * STR + kk + 8]);
            al[3] = *reinterpret_cast<uint32_t*>(&sm[SQL + (wr + lr + 8) * STR + kk + 8]);
            #pragma unroll
            for (int nj = 0; nj < 8; nj++) {
                int n = nj * 8 + lr;
                uint32_t kbh[2], kbl[2];
                kbh[0] = *reinterpret_cast<uint32_t*>(&sm[SKH + n * STR + kk]);
                kbh[1] = *reinterpret_cast<uint32_t*>(&sm[SKH + n * STR + kk + 8]);
                kbl[0] = *reinterpret_cast<uint32_t*>(&sm[SKL + n * STR + kk]);
                kbl[1] = *reinterpret_cast<uint32_t*>(&sm[SKL + n * STR + kk + 8]);
                mma_bf16(accS[nj], ah, kbh);
                mma_bf16(accS[nj], ah, kbl);
                mma_bf16(accS[nj], al, kbh);
            }
        }

        // ---- online softmax on fragments (rows lr, lr+8 of warp tile) ----
        float mx0 = -1e30f, mx1 = -1e30f;
        #pragma unroll
        for (int nj = 0; nj < 8; nj++) {
            mx0 = fmaxf(mx0, fmaxf(accS[nj][0], accS[nj][1]));
            mx1 = fmaxf(mx1, fmaxf(accS[nj][2], accS[nj][3]));
        }
        mx0 = fmaxf(mx0, __shfl_xor_sync(0xffffffffu, mx0, 1, 32));
        mx0 = fmaxf(mx0, __shfl_xor_sync(0xffffffffu, mx0, 2, 32));
        mx1 = fmaxf(mx1, __shfl_xor_sync(0xffffffffu, mx1, 1, 32));
        mx1 = fmaxf(mx1, __shfl_xor_sync(0xffffffffu, mx1, 2, 32));

        float mn0 = fmaxf(m0, mx0), mn1 = fmaxf(m1, mx1);
        float al0 = __expf(m0 - mn0), al1 = __expf(m1 - mn1);
        m0 = mn0; m1 = mn1;

        float s0 = 0.0f, s1 = 0.0f;
        #pragma unroll
        for (int nj = 0; nj < 8; nj++) {
            accS[nj][0] = __expf(accS[nj][0] - mn0);
            accS[nj][1] = __expf(accS[nj][1] - mn0);
            accS[nj][2] = __expf(accS[nj][2] - mn1);
            accS[nj][3] = __expf(accS[nj][3] - mn1);
            s0 += accS[nj][0] + accS[nj][1];
            s1 += accS[nj][2] + accS[nj][3];
        }
        s0 += __shfl_xor_sync(0xffffffffu, s0, 1, 32);
        s0 += __shfl_xor_sync(0xffffffffu, s0, 2, 32);
        s1 += __shfl_xor_sync(0xffffffffu, s1, 1, 32);
        s1 += __shfl_xor_sync(0xffffffffu, s1, 2, 32);
        l0 = l0 * al0 + s0;
        l1 = l1 * al1 + s1;

        #pragma unroll
        for (int nj = 0; nj < 8; nj++) {
            accO[nj][0] *= al0; accO[nj][1] *= al0;
            accO[nj][2] *= al1; accO[nj][3] *= al1;
        }

        // ---- O += P @ V (P in registers; 3-term split) ----
        #pragma unroll
        for (int ksi = 0; ksi < 4; ksi++) {
            const int t0 = 2 * ksi, t1 = 2 * ksi + 1;
            uint32_t ph[4], pl[4];
            {
                float x0 = accS[t0][0], x1 = accS[t0][1];
                float x2 = accS[t0][2], x3 = accS[t0][3];
                float y0 = accS[t1][0], y1 = accS[t1][1];
                float y2 = accS[t1][2], y3 = accS[t1][3];
                ph[0] = pack_bf16x2(x0, x1);
                ph[1] = pack_bf16x2(x2, x3);
                ph[2] = pack_bf16x2(y0, y1);
                ph[3] = pack_bf16x2(y2, y3);
                __nv_bfloat162* hp;
                hp = reinterpret_cast<__nv_bfloat162*>(&ph[0]);
                pl[0] = pack_bf16x2(x0 - __bfloat162float(hp->x), x1 - __bfloat162float(hp->y));
                hp = reinterpret_cast<__nv_bfloat162*>(&ph[1]);
                pl[1] = pack_bf16x2(x2 - __bfloat162float(hp->x), x3 - __bfloat162float(hp->y));
                hp = reinterpret_cast<__nv_bfloat162*>(&ph[2]);
                pl[2] = pack_bf16x2(y0 - __bfloat162float(hp->x), y1 - __bfloat162float(hp->y));
                hp = reinterpret_cast<__nv_bfloat162*>(&ph[3]);
                pl[3] = pack_bf16x2(y2 - __bfloat162float(hp->x), y3 - __bfloat162float(hp->y));
            }
            const int kk = ksi * 16 + lc;
            #pragma unroll
            for (int nj = 0; nj < 8; nj++) {
                int n = nj * 8 + lr;
                uint32_t vbh[2], vbl[2];
                vbh[0] = *reinterpret_cast<uint32_t*>(&sm[SVH + n * STR + kk]);
                vbh[1] = *reinterpret_cast<uint32_t*>(&sm[SVH + n * STR + kk + 8]);
                vbl[0] = *reinterpret_cast<uint32_t*>(&sm[SVL + n * STR + kk]);
                vbl[1] = *reinterpret_cast<uint32_t*>(&sm[SVL + n * STR + kk + 8]);
                mma_bf16(accO[nj], ph, vbh);
                mma_bf16(accO[nj], ph, vbl);
                mma_bf16(accO[nj], pl, vbh);
            }
        }
        __syncthreads();
    }

    // ---- epilogue: normalize, write [b, tok, h*64 + d] ----
    const int b = bh >> 4;
    const int h = bh & 15;
    const float inv0 = 1.0f / l0, inv1 = 1.0f / l1;
    const int tok0 = q0 + wr + lr;
    #pragma unroll
    for (int nj = 0; nj < 8; nj++) {
        int d = nj * 8 + lc;
        long base0 = ((long)(b * SEQ + tok0)) * DM + h * HD + d;
        long base1 = ((long)(b * SEQ + tok0 + 8)) * DM + h * HD + d;
        *reinterpret_cast<float2*>(out + base0) =
            make_float2(accO[nj][0] * inv0, accO[nj][1] * inv0);
        *reinterpret_cast<float2*>(out + base1) =
            make_float2(accO[nj][2] * inv1, accO[nj][3] * inv1);
    }
}

// ---------------------------------------------------------------------------
extern "C" void kernel_launch(void* const* d_in, const int* in_sizes, int n_in,
                              void* d_out, int out_size) {
    const float* tokens = (const float*)d_in[0];   // [2,2048,1024]
    const float* w_qkv  = (const float*)d_in[1];   // [1024,3072]
    const float* b_qkv  = (const float*)d_in[2];   // [3072]
    float* out = (float*)d_out;                    // [2,2048,1024]

    const int attn_smem = ATTN_SMEM_BF16 * (int)sizeof(__nv_bfloat16); // 73728 B
    cudaFuncSetAttribute(attn_mma, cudaFuncAttributeMaxDynamicSharedMemorySize, attn_smem);

    split_a<<<4096, 256>>>(tokens);
    split_w<<<dim3(96, 32), 256>>>(w_qkv);

    dim3 gg(3072 / 128, 4096 / 128);   // (24, 32)
    qkv_mma<<<gg, 256>>>(b_qkv);

    dim3 g2(SEQ / 128, BH);            // (16, 32)
    attn_mma<<<g2, 256, attn_smem>>>(out);
}

// round 13
// speedup vs baseline: 2.6176x; 1.1260x over previous
#include <cuda_runtime.h>
#include <cuda_bf16.h>
#include <cstdint>
#include <math.h>

#define BATCH 2
#define SEQ   2048
#define HEADS 16
#define HD    64
#define DM    1024
#define BH    (BATCH*HEADS)

// ---------------------------------------------------------------------------
// Device scratch (BSS — no allocation)
// ---------------------------------------------------------------------------
__device__ __align__(16) __nv_bfloat16 g_ahi[4096 * 1024];
__device__ __align__(16) __nv_bfloat16 g_alo[4096 * 1024];
__device__ __align__(16) __nv_bfloat16 g_whi[3072 * 1024];
__device__ __align__(16) __nv_bfloat16 g_wlo[3072 * 1024];
// Q/K: [bh][seq][d].  V: TRANSPOSED [bh][d][seq]  (written by qkv_mma epilogue)
__device__ __align__(16) __nv_bfloat16 g_qhi[BH * SEQ * HD];
__device__ __align__(16) __nv_bfloat16 g_qlo[BH * SEQ * HD];
__device__ __align__(16) __nv_bfloat16 g_khi[BH * SEQ * HD];
__device__ __align__(16) __nv_bfloat16 g_klo[BH * SEQ * HD];
__device__ __align__(16) __nv_bfloat16 g_vhi[BH * HD * SEQ];
__device__ __align__(16) __nv_bfloat16 g_vlo[BH * HD * SEQ];

// ---------------------------------------------------------------------------
// Helpers
// ---------------------------------------------------------------------------
__device__ __forceinline__ uint32_t smem_u32(const void* p) {
    uint32_t a;
    asm("{ .reg .u64 t; cvta.to.shared.u64 t, %1; cvt.u32.u64 %0, t; }" : "=r"(a) : "l"(p));
    return a;
}
__device__ __forceinline__ void cpa16(uint32_t dst, const void* src) {
    asm volatile("cp.async.cg.shared.global [%0], [%1], 16;" :: "r"(dst), "l"(src) : "memory");
}
#define CP_COMMIT() asm volatile("cp.async.commit_group;" ::: "memory")
#define CP_WAIT(n)  asm volatile("cp.async.wait_group %0;" :: "n"(n) : "memory")

__device__ __forceinline__ void mma_bf16(float* d, const uint32_t* a, const uint32_t* b) {
    asm volatile(
        "mma.sync.aligned.m16n8k16.row.col.f32.bf16.bf16.f32 "
        "{%0,%1,%2,%3}, {%4,%5,%6,%7}, {%8,%9}, {%0,%1,%2,%3};"
        : "+f"(d[0]), "+f"(d[1]), "+f"(d[2]), "+f"(d[3])
        : "r"(a[0]), "r"(a[1]), "r"(a[2]), "r"(a[3]), "r"(b[0]), "r"(b[1]));
}
__device__ __forceinline__ uint32_t pack_bf16x2(float x0, float x1) {
    __nv_bfloat162 p(__float2bfloat16(x0), __float2bfloat16(x1));
    return *reinterpret_cast<uint32_t*>(&p);
}

// ---------------------------------------------------------------------------
// Split kernels: fp32 -> bf16 hi + bf16 lo
// ---------------------------------------------------------------------------
__global__ __launch_bounds__(256) void split_a(const float* __restrict__ A) {
    int i = blockIdx.x * 256 + threadIdx.x;
    float4 v = reinterpret_cast<const float4*>(A)[i];
    __nv_bfloat16 h0 = __float2bfloat16(v.x), h1 = __float2bfloat16(v.y);
    __nv_bfloat16 h2 = __float2bfloat16(v.z), h3 = __float2bfloat16(v.w);
    __nv_bfloat16 l0 = __float2bfloat16(v.x - __bfloat162float(h0));
    __nv_bfloat16 l1 = __float2bfloat16(v.y - __bfloat162float(h1));
    __nv_bfloat16 l2 = __float2bfloat16(v.z - __bfloat162float(h2));
    __nv_bfloat16 l3 = __float2bfloat16(v.w - __bfloat162float(h3));
    __nv_bfloat162* ph = reinterpret_cast<__nv_bfloat162*>(g_ahi);
    __nv_bfloat162* pl = reinterpret_cast<__nv_bfloat162*>(g_alo);
    ph[2 * i]     = __nv_bfloat162(h0, h1);
    ph[2 * i + 1] = __nv_bfloat162(h2, h3);
    pl[2 * i]     = __nv_bfloat162(l0, l1);
    pl[2 * i + 1] = __nv_bfloat162(l2, l3);
}

__global__ __launch_bounds__(256) void split_w(const float* __restrict__ W) {
    __shared__ float t[32][33];
    const int tx = threadIdx.x & 31, ty = threadIdx.x >> 5;
    const int n0 = blockIdx.x * 32, k0 = blockIdx.y * 32;
    #pragma unroll
    for (int r = 0; r < 32; r += 8)
        t[ty + r][tx] = W[(long)(k0 + ty + r) * 3072 + n0 + tx];
    __syncthreads();
    #pragma unroll
    for (int r = 0; r < 32; r += 8) {
        int n = n0 + ty + r, k = k0 + tx;
        float x = t[tx][ty + r];
        __nv_bfloat16 h = __float2bfloat16(x);
        __nv_bfloat16 l = __float2bfloat16(x - __bfloat162float(h));
        g_whi[(long)n * 1024 + k] = h;
        g_wlo[(long)n * 1024 + k] = l;
    }
}

// ---------------------------------------------------------------------------
// Kernel 1: QKV GEMM via HMMA (R10/R12 measured-good). V written transposed.
// ---------------------------------------------------------------------------
#define KC 32
#define ASTR 40

__global__ __launch_bounds__(256) void qkv_mma(const float* __restrict__ bias) {
    __shared__ __align__(16) __nv_bfloat16 sA[2][128 * ASTR];
    __shared__ __align__(16) __nv_bfloat16 sB[2][128 * ASTR];

    const int tid = threadIdx.x;
    const int wid = tid >> 5, lane = tid & 31;
    const int wm = (wid & 3) * 32;
    const int wn = (wid >> 2) * 64;
    const int bm = blockIdx.y * 128;
    const int bn = blockIdx.x * 128;
    const int lr = lane >> 2;
    const int lc = 2 * (lane & 3);

    float acc[2][8][4];
    #pragma unroll
    for (int mi = 0; mi < 2; mi++)
        #pragma unroll
        for (int nj = 0; nj < 8; nj++)
            #pragma unroll
            for (int q = 0; q < 4; q++) acc[mi][nj][q] = 0.0f;

    for (int ck = 0; ck < DM / KC; ck++) {
        const int k0 = ck * KC;
        #pragma unroll
        for (int i = 0; i < 2; i++) {
            int idx = tid + i * 256;
            int r = idx >> 2, c = (idx & 3) * 8;
            long srcA = (long)(bm + r) * DM + k0 + c;
            long srcB = (long)(bn + r) * DM + k0 + c;
            *reinterpret_cast<uint4*>(&sA[0][r * ASTR + c]) =
                *reinterpret_cast<const uint4*>(g_ahi + srcA);
            *reinterpret_cast<uint4*>(&sA[1][r * ASTR + c]) =
                *reinterpret_cast<const uint4*>(g_alo + srcA);
            *reinterpret_cast<uint4*>(&sB[0][r * ASTR + c]) =
                *reinterpret_cast<const uint4*>(g_whi + srcB);
            *reinterpret_cast<uint4*>(&sB[1][r * ASTR + c]) =
                *reinterpret_cast<const uint4*>(g_wlo + srcB);
        }
        __syncthreads();

        #pragma unroll
        for (int ks = 0; ks < 2; ks++) {
            const int kk = ks * 16 + lc;
            uint32_t ah[2][4], al[2][4];
            #pragma unroll
            for (int mi = 0; mi < 2; mi++) {
                int r = wm + mi * 16 + lr;
                ah[mi][0] = *reinterpret_cast<uint32_t*>(&sA[0][r * ASTR + kk]);
                ah[mi][1] = *reinterpret_cast<uint32_t*>(&sA[0][(r + 8) * ASTR + kk]);
                ah[mi][2] = *reinterpret_cast<uint32_t*>(&sA[0][r * ASTR + kk + 8]);
                ah[mi][3] = *reinterpret_cast<uint32_t*>(&sA[0][(r + 8) * ASTR + kk + 8]);
                al[mi][0] = *reinterpret_cast<uint32_t*>(&sA[1][r * ASTR + kk]);
                al[mi][1] = *reinterpret_cast<uint32_t*>(&sA[1][(r + 8) * ASTR + kk]);
                al[mi][2] = *reinterpret_cast<uint32_t*>(&sA[1][r * ASTR + kk + 8]);
                al[mi][3] = *reinterpret_cast<uint32_t*>(&sA[1][(r + 8) * ASTR + kk + 8]);
            }
            #pragma unroll
            for (int nj = 0; nj < 8; nj++) {
                int n = wn + nj * 8 + lr;
                uint32_t bh2[2], bl2[2];
                bh2[0] = *reinterpret_cast<uint32_t*>(&sB[0][n * ASTR + kk]);
                bh2[1] = *reinterpret_cast<uint32_t*>(&sB[0][n * ASTR + kk + 8]);
                bl2[0] = *reinterpret_cast<uint32_t*>(&sB[1][n * ASTR + kk]);
                bl2[1] = *reinterpret_cast<uint32_t*>(&sB[1][n * ASTR + kk + 8]);
                #pragma unroll
                for (int mi = 0; mi < 2; mi++) {
                    mma_bf16(acc[mi][nj], ah[mi], bh2);
                    mma_bf16(acc[mi][nj], ah[mi], bl2);
                    mma_bf16(acc[mi][nj], al[mi], bh2);
                }
            }
        }
        __syncthreads();
    }

    const int sec = bn >> 10;                    // 0=Q, 1=K, 2=V
    const float scale = (sec == 0) ? 0.125f : 1.0f;
    #pragma unroll
    for (int nj = 0; nj < 8; nj++) {
        int col = bn + wn + nj * 8 + lc;
        int rem = col & 1023;
        int h = rem >> 6, ch = rem & 63;
        float bv0 = bias[col], bv1 = bias[col + 1];
        #pragma unroll
        for (int mi = 0; mi < 2; mi++) {
            #pragma unroll
            for (int half = 0; half < 2; half++) {
                int row = bm + wm + mi * 16 + lr + half * 8;
                int bt = row >> 11, tok = row & 2047;
                float v0 = (acc[mi][nj][half * 2 + 0] + bv0) * scale;
                float v1 = (acc[mi][nj][half * 2 + 1] + bv1) * scale;
                __nv_bfloat16 h0 = __float2bfloat16(v0);
                __nv_bfloat16 h1 = __float2bfloat16(v1);
                __nv_bfloat16 e0 = __float2bfloat16(v0 - __bfloat162float(h0));
                __nv_bfloat16 e1 = __float2bfloat16(v1 - __bfloat162float(h1));
                if (sec == 2) {
                    // V transposed: [bh][d][tok]
                    long bt0 = (((long)(bt * HEADS + h)) * HD + ch) * SEQ + tok;
                    g_vhi[bt0]       = h0;
                    g_vhi[bt0 + SEQ] = h1;
                    g_vlo[bt0]       = e0;
                    g_vlo[bt0 + SEQ] = e1;
                } else {
                    long base = (((long)(bt * HEADS + h)) * SEQ + tok) * HD + ch;
                    __nv_bfloat16* dh = (sec == 0) ? g_qhi : g_khi;
                    __nv_bfloat16* dl = (sec == 0) ? g_qlo : g_klo;
                    *reinterpret_cast<__nv_bfloat162*>(dh + base) = __nv_bfloat162(h0, h1);
                    *reinterpret_cast<__nv_bfloat162*>(dl + base) = __nv_bfloat162(e0, e1);
                }
            }
        }
    }
}

// ---------------------------------------------------------------------------
// Kernel 2: HMMA flash attention, cp.async double-buffered.
// CTA = (bh, 128-q tile), 8 warps. Key-tiles of 64.
// Q fragments hoisted to registers; Q smem recycled as 2nd pipeline buffer.
// ---------------------------------------------------------------------------
#define STR 72
// unit offsets (bf16 units)
#define UQH  0
#define UQL  (128 * STR)                 // 9216
#define BUFSZ (4 * 64 * STR)             // 18432 units (= Q region size)
#define BKH  0
#define BKL  (64 * STR)
#define BVH  (2 * 64 * STR)
#define BVL  (3 * 64 * STR)
#define ATTN_SMEM_UNITS (2 * BUFSZ)      // 36864 units = 73728 B
#define NT   (SEQ / 64)                  // 32 key tiles

__global__ __launch_bounds__(256) void attn_mma(float* __restrict__ out) {
    extern __shared__ __align__(16) __nv_bfloat16 sm[];
    const uint32_t sb = smem_u32(sm);

    const int tid = threadIdx.x;
    const int wid = tid >> 5, lane = tid & 31;
    const int lr = lane >> 2;
    const int lc = 2 * (lane & 3);
    const int bh = blockIdx.y;
    const int q0 = blockIdx.x * 128;
    const int wr = wid * 16;

    const long qoff  = (long)bh * SEQ * HD + (long)q0 * HD;
    const long koff  = (long)bh * SEQ * HD;
    const long vtoff = (long)bh * HD * SEQ;

    // --- group 0: Q loads into region UQH/UQL ---
    {
        #pragma unroll
        for (int i = 0; i < 4; i++) {
            int idx = tid + i * 256;
            int r = idx >> 3, c = (idx & 7) * 8;
            cpa16(sb + (UQH + r * STR + c) * 2, g_qhi + qoff + r * 64 + c);
            cpa16(sb + (UQL + r * STR + c) * 2, g_qlo + qoff + r * 64 + c);
        }
        CP_COMMIT();
    }
    // --- group 1: prefetch tile 0 into buffer 0 (offset BUFSZ) ---
    {
        const uint32_t bb = BUFSZ;
        #pragma unroll
        for (int i = 0; i < 2; i++) {
            int idx = tid + i * 256;
            int r = idx >> 3, c = (idx & 7) * 8;
            cpa16(sb + (bb + BKH + r * STR + c) * 2, g_khi + koff + (long)r * 64 + c);
            cpa16(sb + (bb + BKL + r * STR + c) * 2, g_klo + koff + (long)r * 64 + c);
            cpa16(sb + (bb + BVH + r * STR + c) * 2, g_vhi + vtoff + (long)r * SEQ + c);
            cpa16(sb + (bb + BVL + r * STR + c) * 2, g_vlo + vtoff + (long)r * SEQ + c);
        }
        CP_COMMIT();
    }

    CP_WAIT(1);            // Q landed (tile0 may still be in flight)
    __syncthreads();

    // --- hoist Q fragments ---
    uint32_t qh[4][4], ql[4][4];
    #pragma unroll
    for (int ks = 0; ks < 4; ks++) {
        const int kk = ks * 16 + lc;
        qh[ks][0] = *reinterpret_cast<uint32_t*>(&sm[UQH + (wr + lr) * STR + kk]);
        qh[ks][1] = *reinterpret_cast<uint32_t*>(&sm[UQH + (wr + lr + 8) * STR + kk]);
        qh[ks][2] = *reinterpret_cast<uint32_t*>(&sm[UQH + (wr + lr) * STR + kk + 8]);
        qh[ks][3] = *reinterpret_cast<uint32_t*>(&sm[UQH + (wr + lr + 8) * STR + kk + 8]);
        ql[ks][0] = *reinterpret_cast<uint32_t*>(&sm[UQL + (wr + lr) * STR + kk]);
        ql[ks][1] = *reinterpret_cast<uint32_t*>(&sm[UQL + (wr + lr + 8) * STR + kk]);
        ql[ks][2] = *reinterpret_cast<uint32_t*>(&sm[UQL + (wr + lr) * STR + kk + 8]);
        ql[ks][3] = *reinterpret_cast<uint32_t*>(&sm[UQL + (wr + lr + 8) * STR + kk + 8]);
    }
    __syncthreads();       // all warps done reading Q before buffer1 reuse

    float accO[8][4];
    #pragma unroll
    for (int nj = 0; nj < 8; nj++)
        #pragma unroll
        for (int q = 0; q < 4; q++) accO[nj][q] = 0.0f;
    float m0 = -1e30f, m1 = -1e30f, l0 = 0.0f, l1 = 0.0f;

    for (int t = 0; t < NT; t++) {
        // prefetch next tile into the other buffer
        if (t + 1 < NT) {
            const int kt = (t + 1) * 64;
            const uint32_t bb = ((t + 1) & 1) ? 0u : (uint32_t)BUFSZ;
            #pragma unroll
            for (int i = 0; i < 2; i++) {
                int idx = tid + i * 256;
                int r = idx >> 3, c = (idx & 7) * 8;
                cpa16(sb + (bb + BKH + r * STR + c) * 2, g_khi + koff + (long)(kt + r) * 64 + c);
                cpa16(sb + (bb + BKL + r * STR + c) * 2, g_klo + koff + (long)(kt + r) * 64 + c);
                cpa16(sb + (bb + BVH + r * STR + c) * 2, g_vhi + vtoff + (long)r * SEQ + kt + c);
                cpa16(sb + (bb + BVL + r * STR + c) * 2, g_vlo + vtoff + (long)r * SEQ + kt + c);
            }
            CP_COMMIT();
            CP_WAIT(1);    // current tile ready; next still loading
        } else {
            CP_WAIT(0);
        }
        __syncthreads();

        const uint32_t bb = (t & 1) ? 0u : (uint32_t)BUFSZ;

        // ---- S = Q K^T (3-term) ----
        float accS[8][4];
        #pragma unroll
        for (int nj = 0; nj < 8; nj++)
            #pragma unroll
            for (int q = 0; q < 4; q++) accS[nj][q] = 0.0f;

        #pragma unroll
        for (int ks = 0; ks < 4; ks++) {
            const int kk = ks * 16 + lc;
            #pragma unroll
            for (int nj = 0; nj < 8; nj++) {
                int n = nj * 8 + lr;
                uint32_t kbh[2], kbl[2];
                kbh[0] = *reinterpret_cast<uint32_t*>(&sm[bb + BKH + n * STR + kk]);
                kbh[1] = *reinterpret_cast<uint32_t*>(&sm[bb + BKH + n * STR + kk + 8]);
                kbl[0] = *reinterpret_cast<uint32_t*>(&sm[bb + BKL + n * STR + kk]);
                kbl[1] = *reinterpret_cast<uint32_t*>(&sm[bb + BKL + n * STR + kk + 8]);
                mma_bf16(accS[nj], qh[ks], kbh);
                mma_bf16(accS[nj], qh[ks], kbl);
                mma_bf16(accS[nj], ql[ks], kbh);
            }
        }

        // ---- online softmax ----
        float mx0 = -1e30f, mx1 = -1e30f;
        #pragma unroll
        for (int nj = 0; nj < 8; nj++) {
            mx0 = fmaxf(mx0, fmaxf(accS[nj][0], accS[nj][1]));
            mx1 = fmaxf(mx1, fmaxf(accS[nj][2], accS[nj][3]));
        }
        mx0 = fmaxf(mx0, __shfl_xor_sync(0xffffffffu, mx0, 1, 32));
        mx0 = fmaxf(mx0, __shfl_xor_sync(0xffffffffu, mx0, 2, 32));
        mx1 = fmaxf(mx1, __shfl_xor_sync(0xffffffffu, mx1, 1, 32));
        mx1 = fmaxf(mx1, __shfl_xor_sync(0xffffffffu, mx1, 2, 32));

        float mn0 = fmaxf(m0, mx0), mn1 = fmaxf(m1, mx1);
        float al0 = __expf(m0 - mn0), al1 = __expf(m1 - mn1);
        m0 = mn0; m1 = mn1;

        float s0 = 0.0f, s1 = 0.0f;
        #pragma unroll
        for (int nj = 0; nj < 8; nj++) {
            accS[nj][0] = __expf(accS[nj][0] - mn0);
            accS[nj][1] = __expf(accS[nj][1] - mn0);
            accS[nj][2] = __expf(accS[nj][2] - mn1);
            accS[nj][3] = __expf(accS[nj][3] - mn1);
            s0 += accS[nj][0] + accS[nj][1];
            s1 += accS[nj][2] + accS[nj][3];
        }
        s0 += __shfl_xor_sync(0xffffffffu, s0, 1, 32);
        s0 += __shfl_xor_sync(0xffffffffu, s0, 2, 32);
        s1 += __shfl_xor_sync(0xffffffffu, s1, 1, 32);
        s1 += __shfl_xor_sync(0xffffffffu, s1, 2, 32);
        l0 = l0 * al0 + s0;
        l1 = l1 * al1 + s1;

        #pragma unroll
        for (int nj = 0; nj < 8; nj++) {
            accO[nj][0] *= al0; accO[nj][1] *= al0;
            accO[nj][2] *= al1; accO[nj][3] *= al1;
        }

        // ---- O += P @ V (P in registers, 3-term) ----
        #pragma unroll
        for (int ksi = 0; ksi < 4; ksi++) {
            const int t0 = 2 * ksi, t1 = 2 * ksi + 1;
            uint32_t ph[4], pl[4];
            {
                float x0 = accS[t0][0], x1 = accS[t0][1];
                float x2 = accS[t0][2], x3 = accS[t0][3];
                float y0 = accS[t1][0], y1 = accS[t1][1];
                float y2 = accS[t1][2], y3 = accS[t1][3];
                ph[0] = pack_bf16x2(x0, x1);
                ph[1] = pack_bf16x2(x2, x3);
                ph[2] = pack_bf16x2(y0, y1);
                ph[3] = pack_bf16x2(y2, y3);
                __nv_bfloat162* hp;
                hp = reinterpret_cast<__nv_bfloat162*>(&ph[0]);
                pl[0] = pack_bf16x2(x0 - __bfloat162float(hp->x), x1 - __bfloat162float(hp->y));
                hp = reinterpret_cast<__nv_bfloat162*>(&ph[1]);
                pl[1] = pack_bf16x2(x2 - __bfloat162float(hp->x), x3 - __bfloat162float(hp->y));
                hp = reinterpret_cast<__nv_bfloat162*>(&ph[2]);
                pl[2] = pack_bf16x2(y0 - __bfloat162float(hp->x), y1 - __bfloat162float(hp->y));
                hp = reinterpret_cast<__nv_bfloat162*>(&ph[3]);
                pl[3] = pack_bf16x2(y2 - __bfloat162float(hp->x), y3 - __bfloat162float(hp->y));
            }
            const int kk = ksi * 16 + lc;
            #pragma unroll
            for (int nj = 0; nj < 8; nj++) {
                int n = nj * 8 + lr;
                uint32_t vbh[2], vbl[2];
                vbh[0] = *reinterpret_cast<uint32_t*>(&sm[bb + BVH + n * STR + kk]);
                vbh[1] = *reinterpret_cast<uint32_t*>(&sm[bb + BVH + n * STR + kk + 8]);
                vbl[0] = *reinterpret_cast<uint32_t*>(&sm[bb + BVL + n * STR + kk]);
                vbl[1] = *reinterpret_cast<uint32_t*>(&sm[bb + BVL + n * STR + kk + 8]);
                mma_bf16(accO[nj], ph, vbh);
                mma_bf16(accO[nj], ph, vbl);
                mma_bf16(accO[nj], pl, vbh);
            }
        }
        __syncthreads();   // buffer free for prefetch of t+2
    }

    // ---- epilogue ----
    const int b = bh >> 4;
    const int h = bh & 15;
    const float inv0 = 1.0f / l0, inv1 = 1.0f / l1;
    const int tok0 = q0 + wr + lr;
    #pragma unroll
    for (int nj = 0; nj < 8; nj++) {
        int d = nj * 8 + lc;
        long base0 = ((long)(b * SEQ + tok0)) * DM + h * HD + d;
        long base1 = ((long)(b * SEQ + tok0 + 8)) * DM + h * HD + d;
        *reinterpret_cast<float2*>(out + base0) =
            make_float2(accO[nj][0] * inv0, accO[nj][1] * inv0);
        *reinterpret_cast<float2*>(out + base1) =
            make_float2(accO[nj][2] * inv1, accO[nj][3] * inv1);
    }
}

// ---------------------------------------------------------------------------
extern "C" void kernel_launch(void* const* d_in, const int* in_sizes, int n_in,
                              void* d_out, int out_size) {
    const float* tokens = (const float*)d_in[0];   // [2,2048,1024]
    const float* w_qkv  = (const float*)d_in[1];   // [1024,3072]
    const float* b_qkv  = (const float*)d_in[2];   // [3072]
    float* out = (float*)d_out;                    // [2,2048,1024]

    const int attn_smem = ATTN_SMEM_UNITS * (int)sizeof(__nv_bfloat16); // 73728 B
    cudaFuncSetAttribute(attn_mma, cudaFuncAttributeMaxDynamicSharedMemorySize, attn_smem);

    split_a<<<4096, 256>>>(tokens);
    split_w<<<dim3(96, 32), 256>>>(w_qkv);

    dim3 gg(3072 / 128, 4096 / 128);   // (24, 32)
    qkv_mma<<<gg, 256>>>(b_qkv);

    dim3 g2(SEQ / 128, BH);            // (16, 32)
    attn_mma<<<g2, 256, attn_smem>>>(out);
}

// round 15
// speedup vs baseline: 2.7811x; 1.0625x over previous
#include <cuda_runtime.h>
#include <cuda_bf16.h>
#include <cstdint>
#include <math.h>

#define BATCH 2
#define SEQ   2048
#define HEADS 16
#define HD    64
#define DM    1024
#define BH    (BATCH*HEADS)

// ---------------------------------------------------------------------------
// Device scratch (BSS — no allocation)
// ---------------------------------------------------------------------------
__device__ __align__(16) __nv_bfloat16 g_ahi[4096 * 1024];
__device__ __align__(16) __nv_bfloat16 g_alo[4096 * 1024];
__device__ __align__(16) __nv_bfloat16 g_whi[3072 * 1024];
__device__ __align__(16) __nv_bfloat16 g_wlo[3072 * 1024];
// Q/K: [bh][seq][d].  V: TRANSPOSED [bh][d][seq]
__device__ __align__(16) __nv_bfloat16 g_qhi[BH * SEQ * HD];
__device__ __align__(16) __nv_bfloat16 g_qlo[BH * SEQ * HD];
__device__ __align__(16) __nv_bfloat16 g_khi[BH * SEQ * HD];
__device__ __align__(16) __nv_bfloat16 g_klo[BH * SEQ * HD];
__device__ __align__(16) __nv_bfloat16 g_vhi[BH * HD * SEQ];
__device__ __align__(16) __nv_bfloat16 g_vlo[BH * HD * SEQ];

// ---------------------------------------------------------------------------
// Helpers
// ---------------------------------------------------------------------------
__device__ __forceinline__ uint32_t smem_u32(const void* p) {
    uint32_t a;
    asm("{ .reg .u64 t; cvta.to.shared.u64 t, %1; cvt.u32.u64 %0, t; }" : "=r"(a) : "l"(p));
    return a;
}
__device__ __forceinline__ void cpa16(uint32_t dst, const void* src) {
    asm volatile("cp.async.cg.shared.global [%0], [%1], 16;" :: "r"(dst), "l"(src) : "memory");
}
#define CP_COMMIT() asm volatile("cp.async.commit_group;" ::: "memory")
#define CP_WAIT(n)  asm volatile("cp.async.wait_group %0;" :: "n"(n) : "memory")

__device__ __forceinline__ void mma_bf16(float* d, const uint32_t* a, const uint32_t* b) {
    asm volatile(
        "mma.sync.aligned.m16n8k16.row.col.f32.bf16.bf16.f32 "
        "{%0,%1,%2,%3}, {%4,%5,%6,%7}, {%8,%9}, {%0,%1,%2,%3};"
        : "+f"(d[0]), "+f"(d[1]), "+f"(d[2]), "+f"(d[3])
        : "r"(a[0]), "r"(a[1]), "r"(a[2]), "r"(a[3]), "r"(b[0]), "r"(b[1]));
}
__device__ __forceinline__ uint32_t pack_bf16x2(float x0, float x1) {
    __nv_bfloat162 p(__float2bfloat16(x0), __float2bfloat16(x1));
    return *reinterpret_cast<uint32_t*>(&p);
}

// ---------------------------------------------------------------------------
// Split kernels: fp32 -> bf16 hi + bf16 lo
// ---------------------------------------------------------------------------
__global__ __launch_bounds__(256) void split_a(const float* __restrict__ A) {
    int i = blockIdx.x * 256 + threadIdx.x;
    float4 v = reinterpret_cast<const float4*>(A)[i];
    __nv_bfloat16 h0 = __float2bfloat16(v.x), h1 = __float2bfloat16(v.y);
    __nv_bfloat16 h2 = __float2bfloat16(v.z), h3 = __float2bfloat16(v.w);
    __nv_bfloat16 l0 = __float2bfloat16(v.x - __bfloat162float(h0));
    __nv_bfloat16 l1 = __float2bfloat16(v.y - __bfloat162float(h1));
    __nv_bfloat16 l2 = __float2bfloat16(v.z - __bfloat162float(h2));
    __nv_bfloat16 l3 = __float2bfloat16(v.w - __bfloat162float(h3));
    __nv_bfloat162* ph = reinterpret_cast<__nv_bfloat162*>(g_ahi);
    __nv_bfloat162* pl = reinterpret_cast<__nv_bfloat162*>(g_alo);
    ph[2 * i]     = __nv_bfloat162(h0, h1);
    ph[2 * i + 1] = __nv_bfloat162(h2, h3);
    pl[2 * i]     = __nv_bfloat162(l0, l1);
    pl[2 * i + 1] = __nv_bfloat162(l2, l3);
}

__global__ __launch_bounds__(256) void split_w(const float* __restrict__ W) {
    __shared__ float t[32][33];
    const int tx = threadIdx.x & 31, ty = threadIdx.x >> 5;
    const int n0 = blockIdx.x * 32, k0 = blockIdx.y * 32;
    #pragma unroll
    for (int r = 0; r < 32; r += 8)
        t[ty + r][tx] = W[(long)(k0 + ty + r) * 3072 + n0 + tx];
    __syncthreads();
    #pragma unroll
    for (int r = 0; r < 32; r += 8) {
        int n = n0 + ty + r, k = k0 + tx;
        float x = t[tx][ty + r];
        __nv_bfloat16 h = __float2bfloat16(x);
        __nv_bfloat16 l = __float2bfloat16(x - __bfloat162float(h));
        g_whi[(long)n * 1024 + k] = h;
        g_wlo[(long)n * 1024 + k] = l;
    }
}

// ---------------------------------------------------------------------------
// Kernel 1: QKV GEMM via HMMA, cp.async double-buffered.
// CTA 128x128, 8 warps (4m x 2n). K-chunks of 32, 2-stage pipeline.
// Q scale folds 0.125 * log2(e) so attention softmax can use exp2.
// ---------------------------------------------------------------------------
#define KC 32
#define ASTR 40
#define QSTAGE (4 * 128 * ASTR)          // bf16 units per stage (AH,AL,BH,BL)
#define QAH 0
#define QAL (128 * ASTR)
#define QBH (2 * 128 * ASTR)
#define QBL (3 * 128 * ASTR)
#define QKV_SMEM_B (2 * QSTAGE * 2)      // 81920 bytes
#define QSCALE (0.125f * 1.4426950408889634f)

__global__ __launch_bounds__(256) void qkv_mma(const float* __restrict__ bias) {
    extern __shared__ __align__(16) __nv_bfloat16 qs[];
    const uint32_t sb = smem_u32(qs);

    const int tid = threadIdx.x;
    const int wid = tid >> 5, lane = tid & 31;
    const int wm = (wid & 3) * 32;
    const int wn = (wid >> 2) * 64;
    const int bm = blockIdx.y * 128;
    const int bn = blockIdx.x * 128;
    const int lr = lane >> 2;
    const int lc = 2 * (lane & 3);

    float acc[2][8][4];
    #pragma unroll
    for (int mi = 0; mi < 2; mi++)
        #pragma unroll
        for (int nj = 0; nj < 8; nj++)
            #pragma unroll
            for (int q = 0; q < 4; q++) acc[mi][nj][q] = 0.0f;

    // prefetch chunk 0 into stage 0
    {
        #pragma unroll
        for (int i = 0; i < 2; i++) {
            int idx = tid + i * 256;
            int r = idx >> 2, c = (idx & 3) * 8;
            long srcA = (long)(bm + r) * DM + c;
            long srcB = (long)(bn + r) * DM + c;
            cpa16(sb + (QAH + r * ASTR + c) * 2, g_ahi + srcA);
            cpa16(sb + (QAL + r * ASTR + c) * 2, g_alo + srcA);
            cpa16(sb + (QBH + r * ASTR + c) * 2, g_whi + srcB);
            cpa16(sb + (QBL + r * ASTR + c) * 2, g_wlo + srcB);
        }
        CP_COMMIT();
    }

    for (int ck = 0; ck < DM / KC; ck++) {
        if (ck + 1 < DM / KC) {
            const int k0 = (ck + 1) * KC;
            const uint32_t st = ((ck + 1) & 1) * QSTAGE;
            #pragma unroll
            for (int i = 0; i < 2; i++) {
                int idx = tid + i * 256;
                int r = idx >> 2, c = (idx & 3) * 8;
                long srcA = (long)(bm + r) * DM + k0 + c;
                long srcB = (long)(bn + r) * DM + k0 + c;
                cpa16(sb + (st + QAH + r * ASTR + c) * 2, g_ahi + srcA);
                cpa16(sb + (st + QAL + r * ASTR + c) * 2, g_alo + srcA);
                cpa16(sb + (st + QBH + r * ASTR + c) * 2, g_whi + srcB);
                cpa16(sb + (st + QBL + r * ASTR + c) * 2, g_wlo + srcB);
            }
            CP_COMMIT();
            CP_WAIT(1);
        } else {
            CP_WAIT(0);
        }
        __syncthreads();

        const uint32_t st = (ck & 1) * QSTAGE;
        #pragma unroll
        for (int ks = 0; ks < 2; ks++) {
            const int kk = ks * 16 + lc;
            uint32_t ah[2][4], al[2][4];
            #pragma unroll
            for (int mi = 0; mi < 2; mi++) {
                int r = wm + mi * 16 + lr;
                ah[mi][0] = *reinterpret_cast<uint32_t*>(&qs[st + QAH + r * ASTR + kk]);
                ah[mi][1] = *reinterpret_cast<uint32_t*>(&qs[st + QAH + (r + 8) * ASTR + kk]);
                ah[mi][2] = *reinterpret_cast<uint32_t*>(&qs[st + QAH + r * ASTR + kk + 8]);
                ah[mi][3] = *reinterpret_cast<uint32_t*>(&qs[st + QAH + (r + 8) * ASTR + kk + 8]);
                al[mi][0] = *reinterpret_cast<uint32_t*>(&qs[st + QAL + r * ASTR + kk]);
                al[mi][1] = *reinterpret_cast<uint32_t*>(&qs[st + QAL + (r + 8) * ASTR + kk]);
                al[mi][2] = *reinterpret_cast<uint32_t*>(&qs[st + QAL + r * ASTR + kk + 8]);
                al[mi][3] = *reinterpret_cast<uint32_t*>(&qs[st + QAL + (r + 8) * ASTR + kk + 8]);
            }
            #pragma unroll
            for (int nj = 0; nj < 8; nj++) {
                int n = wn + nj * 8 + lr;
                uint32_t bh2[2], bl2[2];
                bh2[0] = *reinterpret_cast<uint32_t*>(&qs[st + QBH + n * ASTR + kk]);
                bh2[1] = *reinterpret_cast<uint32_t*>(&qs[st + QBH + n * ASTR + kk + 8]);
                bl2[0] = *reinterpret_cast<uint32_t*>(&qs[st + QBL + n * ASTR + kk]);
                bl2[1] = *reinterpret_cast<uint32_t*>(&qs[st + QBL + n * ASTR + kk + 8]);
                #pragma unroll
                for (int mi = 0; mi < 2; mi++) {
                    mma_bf16(acc[mi][nj], ah[mi], bh2);
                    mma_bf16(acc[mi][nj], ah[mi], bl2);
                    mma_bf16(acc[mi][nj], al[mi], bh2);
                }
            }
        }
        __syncthreads();
    }

    const int sec = bn >> 10;                    // 0=Q, 1=K, 2=V
    const float scale = (sec == 0) ? QSCALE : 1.0f;
    #pragma unroll
    for (int nj = 0; nj < 8; nj++) {
        int col = bn + wn + nj * 8 + lc;
        int rem = col & 1023;
        int h = rem >> 6, ch = rem & 63;
        float bv0 = bias[col], bv1 = bias[col + 1];
        #pragma unroll
        for (int mi = 0; mi < 2; mi++) {
            #pragma unroll
            for (int half = 0; half < 2; half++) {
                int row = bm + wm + mi * 16 + lr + half * 8;
                int bt = row >> 11, tok = row & 2047;
                float v0 = (acc[mi][nj][half * 2 + 0] + bv0) * scale;
                float v1 = (acc[mi][nj][half * 2 + 1] + bv1) * scale;
                __nv_bfloat16 h0 = __float2bfloat16(v0);
                __nv_bfloat16 h1 = __float2bfloat16(v1);
                __nv_bfloat16 e0 = __float2bfloat16(v0 - __bfloat162float(h0));
                __nv_bfloat16 e1 = __float2bfloat16(v1 - __bfloat162float(h1));
                if (sec == 2) {
                    long bt0 = (((long)(bt * HEADS + h)) * HD + ch) * SEQ + tok;
                    g_vhi[bt0]       = h0;
                    g_vhi[bt0 + SEQ] = h1;
                    g_vlo[bt0]       = e0;
                    g_vlo[bt0 + SEQ] = e1;
                } else {
                    long base = (((long)(bt * HEADS + h)) * SEQ + tok) * HD + ch;
                    __nv_bfloat16* dh = (sec == 0) ? g_qhi : g_khi;
                    __nv_bfloat16* dl = (sec == 0) ? g_qlo : g_klo;
                    *reinterpret_cast<__nv_bfloat162*>(dh + base) = __nv_bfloat162(h0, h1);
                    *reinterpret_cast<__nv_bfloat162*>(dl + base) = __nv_bfloat162(e0, e1);
                }
            }
        }
    }
}

// ---------------------------------------------------------------------------
// Kernel 2: HMMA flash attention, cp.async double-buffered (R13 measured-good).
// Scores are pre-scaled by log2(e) -> softmax uses exp2f.
// ---------------------------------------------------------------------------
#define STR 72
#define UQH  0
#define UQL  (128 * STR)
#define BUFSZ (4 * 64 * STR)
#define BKH  0
#define BKL  (64 * STR)
#define BVH  (2 * 64 * STR)
#define BVL  (3 * 64 * STR)
#define ATTN_SMEM_UNITS (2 * BUFSZ)
#define NT   (SEQ / 64)

__global__ __launch_bounds__(256) void attn_mma(float* __restrict__ out) {
    extern __shared__ __align__(16) __nv_bfloat16 sm[];
    const uint32_t sb = smem_u32(sm);

    const int tid = threadIdx.x;
    const int wid = tid >> 5, lane = tid & 31;
    const int lr = lane >> 2;
    const int lc = 2 * (lane & 3);
    const int bh = blockIdx.y;
    const int q0 = blockIdx.x * 128;
    const int wr = wid * 16;

    const long qoff  = (long)bh * SEQ * HD + (long)q0 * HD;
    const long koff  = (long)bh * SEQ * HD;
    const long vtoff = (long)bh * HD * SEQ;

    {
        #pragma unroll
        for (int i = 0; i < 4; i++) {
            int idx = tid + i * 256;
            int r = idx >> 3, c = (idx & 7) * 8;
            cpa16(sb + (UQH + r * STR + c) * 2, g_qhi + qoff + r * 64 + c);
            cpa16(sb + (UQL + r * STR + c) * 2, g_qlo + qoff + r * 64 + c);
        }
        CP_COMMIT();
    }
    {
        const uint32_t bb = BUFSZ;
        #pragma unroll
        for (int i = 0; i < 2; i++) {
            int idx = tid + i * 256;
            int r = idx >> 3, c = (idx & 7) * 8;
            cpa16(sb + (bb + BKH + r * STR + c) * 2, g_khi + koff + (long)r * 64 + c);
            cpa16(sb + (bb + BKL + r * STR + c) * 2, g_klo + koff + (long)r * 64 + c);
            cpa16(sb + (bb + BVH + r * STR + c) * 2, g_vhi + vtoff + (long)r * SEQ + c);
            cpa16(sb + (bb + BVL + r * STR + c) * 2, g_vlo + vtoff + (long)r * SEQ + c);
        }
        CP_COMMIT();
    }

    CP_WAIT(1);
    __syncthreads();

    uint32_t qh[4][4], ql[4][4];
    #pragma unroll
    for (int ks = 0; ks < 4; ks++) {
        const int kk = ks * 16 + lc;
        qh[ks][0] = *reinterpret_cast<uint32_t*>(&sm[UQH + (wr + lr) * STR + kk]);
        qh[ks][1] = *reinterpret_cast<uint32_t*>(&sm[UQH + (wr + lr + 8) * STR + kk]);
        qh[ks][2] = *reinterpret_cast<uint32_t*>(&sm[UQH + (wr + lr) * STR + kk + 8]);
        qh[ks][3] = *reinterpret_cast<uint32_t*>(&sm[UQH + (wr + lr + 8) * STR + kk + 8]);
        ql[ks][0] = *reinterpret_cast<uint32_t*>(&sm[UQL + (wr + lr) * STR + kk]);
        ql[ks][1] = *reinterpret_cast<uint32_t*>(&sm[UQL + (wr + lr + 8) * STR + kk]);
        ql[ks][2] = *reinterpret_cast<uint32_t*>(&sm[UQL + (wr + lr) * STR + kk + 8]);
        ql[ks][3] = *reinterpret_cast<uint32_t*>(&sm[UQL + (wr + lr + 8) * STR + kk + 8]);
    }
    __syncthreads();

    float accO[8][4];
    #pragma unroll
    for (int nj = 0; nj < 8; nj++)
        #pragma unroll
        for (int q = 0; q < 4; q++) accO[nj][q] = 0.0f;
    float m0 = -1e30f, m1 = -1e30f, l0 = 0.0f, l1 = 0.0f;

    for (int t = 0; t < NT; t++) {
        if (t + 1 < NT) {
            const int kt = (t + 1) * 64;
            const uint32_t bb = ((t + 1) & 1) ? 0u : (uint32_t)BUFSZ;
            #pragma unroll
            for (int i = 0; i < 2; i++) {
                int idx = tid + i * 256;
                int r = idx >> 3, c = (idx & 7) * 8;
                cpa16(sb + (bb + BKH + r * STR + c) * 2, g_khi + koff + (long)(kt + r) * 64 + c);
                cpa16(sb + (bb + BKL + r * STR + c) * 2, g_klo + koff + (long)(kt + r) * 64 + c);
                cpa16(sb + (bb + BVH + r * STR + c) * 2, g_vhi + vtoff + (long)r * SEQ + kt + c);
                cpa16(sb + (bb + BVL + r * STR + c) * 2, g_vlo + vtoff + (long)r * SEQ + kt + c);
            }
            CP_COMMIT();
            CP_WAIT(1);
        } else {
            CP_WAIT(0);
        }
        __syncthreads();

        const uint32_t bb = (t & 1) ? 0u : (uint32_t)BUFSZ;

        float accS[8][4];
        #pragma unroll
        for (int nj = 0; nj < 8; nj++)
            #pragma unroll
            for (int q = 0; q < 4; q++) accS[nj][q] = 0.0f;

        #pragma unroll
        for (int ks = 0; ks < 4; ks++) {
            const int kk = ks * 16 + lc;
            #pragma unroll
            for (int nj = 0; nj < 8; nj++) {
                int n = nj * 8 + lr;
                uint32_t kbh[2], kbl[2];
                kbh[0] = *reinterpret_cast<uint32_t*>(&sm[bb + BKH + n * STR + kk]);
                kbh[1] = *reinterpret_cast<uint32_t*>(&sm[bb + BKH + n * STR + kk + 8]);
                kbl[0] = *reinterpret_cast<uint32_t*>(&sm[bb + BKL + n * STR + kk]);
                kbl[1] = *reinterpret_cast<uint32_t*>(&sm[bb + BKL + n * STR + kk + 8]);
                mma_bf16(accS[nj], qh[ks], kbh);
                mma_bf16(accS[nj], qh[ks], kbl);
                mma_bf16(accS[nj], ql[ks], kbh);
            }
        }

        float mx0 = -1e30f, mx1 = -1e30f;
        #pragma unroll
        for (int nj = 0; nj < 8; nj++) {
            mx0 = fmaxf(mx0, fmaxf(accS[nj][0], accS[nj][1]));
            mx1 = fmaxf(mx1, fmaxf(accS[nj][2], accS[nj][3]));
        }
        mx0 = fmaxf(mx0, __shfl_xor_sync(0xffffffffu, mx0, 1, 32));
        mx0 = fmaxf(mx0, __shfl_xor_sync(0xffffffffu, mx0, 2, 32));
        mx1 = fmaxf(mx1, __shfl_xor_sync(0xffffffffu, mx1, 1, 32));
        mx1 = fmaxf(mx1, __shfl_xor_sync(0xffffffffu, mx1, 2, 32));

        float mn0 = fmaxf(m0, mx0), mn1 = fmaxf(m1, mx1);
        float al0 = exp2f(m0 - mn0), al1 = exp2f(m1 - mn1);
        m0 = mn0; m1 = mn1;

        float s0 = 0.0f, s1 = 0.0f;
        #pragma unroll
        for (int nj = 0; nj < 8; nj++) {
            accS[nj][0] = exp2f(accS[nj][0] - mn0);
            accS[nj][1] = exp2f(accS[nj][1] - mn0);
            accS[nj][2] = exp2f(accS[nj][2] - mn1);
            accS[nj][3] = exp2f(accS[nj][3] - mn1);
            s0 += accS[nj][0] + accS[nj][1];
            s1 += accS[nj][2] + accS[nj][3];
        }
        s0 += __shfl_xor_sync(0xffffffffu, s0, 1, 32);
        s0 += __shfl_xor_sync(0xffffffffu, s0, 2, 32);
        s1 += __shfl_xor_sync(0xffffffffu, s1, 1, 32);
        s1 += __shfl_xor_sync(0xffffffffu, s1, 2, 32);
        l0 = l0 * al0 + s0;
        l1 = l1 * al1 + s1;

        #pragma unroll
        for (int nj = 0; nj < 8; nj++) {
            accO[nj][0] *= al0; accO[nj][1] *= al0;
            accO[nj][2] *= al1; accO[nj][3] *= al1;
        }

        #pragma unroll
        for (int ksi = 0; ksi < 4; ksi++) {
            const int t0 = 2 * ksi, t1 = 2 * ksi + 1;
            uint32_t ph[4], pl[4];
            {
                float x0 = accS[t0][0], x1 = accS[t0][1];
                float x2 = accS[t0][2], x3 = accS[t0][3];
                float y0 = accS[t1][0], y1 = accS[t1][1];
                float y2 = accS[t1][2], y3 = accS[t1][3];
                ph[0] = pack_bf16x2(x0, x1);
                ph[1] = pack_bf16x2(x2, x3);
                ph[2] = pack_bf16x2(y0, y1);
                ph[3] = pack_bf16x2(y2, y3);
                __nv_bfloat162* hp;
                hp = reinterpret_cast<__nv_bfloat162*>(&ph[0]);
                pl[0] = pack_bf16x2(x0 - __bfloat162float(hp->x), x1 - __bfloat162float(hp->y));
                hp = reinterpret_cast<__nv_bfloat162*>(&ph[1]);
                pl[1] = pack_bf16x2(x2 - __bfloat162float(hp->x), x3 - __bfloat162float(hp->y));
                hp = reinterpret_cast<__nv_bfloat162*>(&ph[2]);
                pl[2] = pack_bf16x2(y0 - __bfloat162float(hp->x), y1 - __bfloat162float(hp->y));
                hp = reinterpret_cast<__nv_bfloat162*>(&ph[3]);
                pl[3] = pack_bf16x2(y2 - __bfloat162float(hp->x), y3 - __bfloat162float(hp->y));
            }
            const int kk = ksi * 16 + lc;
            #pragma unroll
            for (int nj = 0; nj < 8; nj++) {
                int n = nj * 8 + lr;
                uint32_t vbh[2], vbl[2];
                vbh[0] = *reinterpret_cast<uint32_t*>(&sm[bb + BVH + n * STR + kk]);
                vbh[1] = *reinterpret_cast<uint32_t*>(&sm[bb + BVH + n * STR + kk + 8]);
                vbl[0] = *reinterpret_cast<uint32_t*>(&sm[bb + BVL + n * STR + kk]);
                vbl[1] = *reinterpret_cast<uint32_t*>(&sm[bb + BVL + n * STR + kk + 8]);
                mma_bf16(accO[nj], ph, vbh);
                mma_bf16(accO[nj], ph, vbl);
                mma_bf16(accO[nj], pl, vbh);
            }
        }
        __syncthreads();
    }

    const int b = bh >> 4;
    const int h = bh & 15;
    const float inv0 = 1.0f / l0, inv1 = 1.0f / l1;
    const int tok0 = q0 + wr + lr;
    #pragma unroll
    for (int nj = 0; nj < 8; nj++) {
        int d = nj * 8 + lc;
        long base0 = ((long)(b * SEQ + tok0)) * DM + h * HD + d;
        long base1 = ((long)(b * SEQ + tok0 + 8)) * DM + h * HD + d;
        *reinterpret_cast<float2*>(out + base0) =
            make_float2(accO[nj][0] * inv0, accO[nj][1] * inv0);
        *reinterpret_cast<float2*>(out + base1) =
            make_float2(accO[nj][2] * inv1, accO[nj][3] * inv1);
    }
}

// ---------------------------------------------------------------------------
extern "C" void kernel_launch(void* const* d_in, const int* in_sizes, int n_in,
                              void* d_out, int out_size) {
    const float* tokens = (const float*)d_in[0];   // [2,2048,1024]
    const float* w_qkv  = (const float*)d_in[1];   // [1024,3072]
    const float* b_qkv  = (const float*)d_in[2];   // [3072]
    float* out = (float*)d_out;                    // [2,2048,1024]

    cudaFuncSetAttribute(qkv_mma, cudaFuncAttributeMaxDynamicSharedMemorySize, QKV_SMEM_B);
    const int attn_smem = ATTN_SMEM_UNITS * (int)sizeof(__nv_bfloat16); // 73728 B
    cudaFuncSetAttribute(attn_mma, cudaFuncAttributeMaxDynamicSharedMemorySize, attn_smem);

    split_a<<<4096, 256>>>(tokens);
    split_w<<<dim3(96, 32), 256>>>(w_qkv);

    dim3 gg(3072 / 128, 4096 / 128);   // (24, 32)
    qkv_mma<<<gg, 256, QKV_SMEM_B>>>(b_qkv);

    dim3 g2(SEQ / 128, BH);            // (16, 32)
    attn_mma<<<g2, 256, attn_smem>>>(out);
}